// round 3
// baseline (speedup 1.0000x reference)
#include <cuda_runtime.h>
#include <cuda_bf16.h>
#include <math.h>

// ---------------------------------------------------------------------------
// AttentionLM: embed+pos -> gelu -> per-head QKV proj -> softmax attention
// (buggy /D scaling, no mask) -> concat heads -> lm head (relu(zW+b))
// Shapes: B=2 S=2048 E=1024 H=16 D=64 V=32000
// ---------------------------------------------------------------------------

#define B_  2
#define S_  2048
#define E_  1024
#define H_  16
#define D_  64
#define V_  32000
#define BS_ (B_ * S_)          // 4096
#define HD_ (H_ * D_)          // 1024

// scratch (no cudaMalloc allowed) — 5 x 16 MB
__device__ float g_h[BS_ * E_];
__device__ float g_q[B_ * H_ * S_ * D_];
__device__ float g_k[B_ * H_ * S_ * D_];
__device__ float g_v[B_ * H_ * S_ * D_];
__device__ float g_z[BS_ * HD_];

__device__ __forceinline__ float gelu_erf(float v) {
    return 0.5f * v * (1.0f + erff(v * 0.70710678118654752f));
}

// ---------------------------------------------------------------------------
// K1: h[b,s,:] = gelu(embed_table[x[b,s],:] + pos_table[s,:])
// grid = 4096 blocks (one token each), 256 threads
// ---------------------------------------------------------------------------
__global__ void embed_gelu_kernel(const int* __restrict__ x,
                                  const float* __restrict__ emb,
                                  const float* __restrict__ pos) {
    int t = blockIdx.x;                 // flattened b*S+s
    int s = t & (S_ - 1);
    int row = x[t];
    const float4* e4 = reinterpret_cast<const float4*>(emb + (size_t)row * E_);
    const float4* p4 = reinterpret_cast<const float4*>(pos + (size_t)s * E_);
    float4* h4 = reinterpret_cast<float4*>(g_h + (size_t)t * E_);
    int i = threadIdx.x;                // E_/4 = 256 float4 per token
    float4 a = e4[i], b = p4[i], r;
    r.x = gelu_erf(a.x + b.x);
    r.y = gelu_erf(a.y + b.y);
    r.z = gelu_erf(a.z + b.z);
    r.w = gelu_erf(a.w + b.w);
    h4[i] = r;
}

// ---------------------------------------------------------------------------
// K2: q/k/v[b,h,s,d] = sum_e h[b,s,e] * w[h,e,d]
// grid = (BS/64, H, 3), 256 threads, 64x64 tile, BK=16, 4x4 micro-tile
// ---------------------------------------------------------------------------
__global__ void qkv_kernel(const float* __restrict__ wq,
                           const float* __restrict__ wk,
                           const float* __restrict__ wv) {
    __shared__ float As[16][64];   // [k][row]
    __shared__ float Bs[16][64];   // [k][d]

    int rb   = blockIdx.x;         // row tile of flattened bs
    int h    = blockIdx.y;
    int proj = blockIdx.z;
    const float* w = (proj == 0 ? wq : proj == 1 ? wk : wv) + (size_t)h * E_ * D_;
    float* outbuf  = (proj == 0 ? g_q : proj == 1 ? g_k : g_v);

    int tid = threadIdx.x, ty = tid >> 4, tx = tid & 15;
    const float* hp = g_h + (size_t)rb * 64 * E_;

    float acc[4][4];
#pragma unroll
    for (int i = 0; i < 4; i++)
#pragma unroll
        for (int j = 0; j < 4; j++) acc[i][j] = 0.0f;

    for (int k0 = 0; k0 < E_; k0 += 16) {
        {   // A: 64 rows x 16 k, transposed store
            int r = tid >> 2, kk = (tid & 3) << 2;
            float4 av = *reinterpret_cast<const float4*>(hp + (size_t)r * E_ + k0 + kk);
            As[kk + 0][r] = av.x; As[kk + 1][r] = av.y;
            As[kk + 2][r] = av.z; As[kk + 3][r] = av.w;
        }
        {   // B: 16 k x 64 d, direct
            int k = tid >> 4, d4 = (tid & 15) << 2;
            *reinterpret_cast<float4*>(&Bs[k][d4]) =
                *reinterpret_cast<const float4*>(w + (size_t)(k0 + k) * D_ + d4);
        }
        __syncthreads();
#pragma unroll
        for (int k = 0; k < 16; k++) {
            float a[4], bv[4];
#pragma unroll
            for (int i = 0; i < 4; i++) a[i] = As[k][ty * 4 + i];
#pragma unroll
            for (int j = 0; j < 4; j++) bv[j] = Bs[k][tx * 4 + j];
#pragma unroll
            for (int i = 0; i < 4; i++)
#pragma unroll
                for (int j = 0; j < 4; j++) acc[i][j] += a[i] * bv[j];
        }
        __syncthreads();
    }
#pragma unroll
    for (int i = 0; i < 4; i++) {
        int row = rb * 64 + ty * 4 + i;       // flattened bs
        int b   = row >> 11;                  // /2048
        int s   = row & (S_ - 1);
        float* op = outbuf + (((size_t)(b * H_ + h) * S_) + s) * D_ + tx * 4;
#pragma unroll
        for (int j = 0; j < 4; j++) op[j] = acc[i][j];
    }
}

// ---------------------------------------------------------------------------
// K3: flash attention, no mask, scores / 64 (faithful buggy double-scale).
// grid = (S/64, H, B), 256 threads (16x16), 64 q-rows per block,
// K/V streamed in 64-row tiles. Output written as z[b,s,h*64+d].
// ---------------------------------------------------------------------------
__global__ void attn_kernel() {
    __shared__ float q_s[64 * 64];
    __shared__ float kp_s[64 * 64];   // K transposed [d][col]; reused as P [row][col]
    __shared__ float v_s[64 * 64];    // [j][c]

    int qt = blockIdx.x, h = blockIdx.y, b = blockIdx.z;
    const float* qp = g_q + (((size_t)(b * H_ + h) * S_) + qt * 64) * D_;
    const float* kp = g_k + ((size_t)(b * H_ + h) * S_) * D_;
    const float* vp = g_v + ((size_t)(b * H_ + h) * S_) * D_;

    int tid = threadIdx.x, ty = tid >> 4, tx = tid & 15;

    // load Q tile (64x64 row-major)
    for (int i = tid; i < 64 * 64 / 4; i += 256)
        reinterpret_cast<float4*>(q_s)[i] = reinterpret_cast<const float4*>(qp)[i];

    float m[4], l[4], acc[4][4];
#pragma unroll
    for (int r = 0; r < 4; r++) {
        m[r] = -INFINITY; l[r] = 0.0f;
#pragma unroll
        for (int c = 0; c < 4; c++) acc[r][c] = 0.0f;
    }

    for (int kt = 0; kt < S_ / 64; kt++) {
        __syncthreads();   // prior PV reads done before overwrite
        // K tile transposed: kp_s[d][col] = K[kt*64+col][d]
        for (int i = tid; i < 64 * 64; i += 256) {
            int col = i >> 6, d = i & 63;
            kp_s[d * 64 + col] = kp[(size_t)(kt * 64 + col) * D_ + d];
        }
        // V tile direct
        for (int i = tid; i < 64 * 64 / 4; i += 256)
            reinterpret_cast<float4*>(v_s)[i] =
                reinterpret_cast<const float4*>(vp + (size_t)kt * 64 * D_)[i];
        __syncthreads();

        // scores s[r][c] = (q_row . k_col) / 64
        float s[4][4];
#pragma unroll
        for (int r = 0; r < 4; r++)
#pragma unroll
            for (int c = 0; c < 4; c++) s[r][c] = 0.0f;
        for (int d = 0; d < 64; d++) {
            float a[4], bv[4];
#pragma unroll
            for (int r = 0; r < 4; r++) a[r] = q_s[(ty * 4 + r) * 64 + d];
#pragma unroll
            for (int c = 0; c < 4; c++) bv[c] = kp_s[d * 64 + tx * 4 + c];
#pragma unroll
            for (int r = 0; r < 4; r++)
#pragma unroll
                for (int c = 0; c < 4; c++) s[r][c] += a[r] * bv[c];
        }
#pragma unroll
        for (int r = 0; r < 4; r++)
#pragma unroll
            for (int c = 0; c < 4; c++) s[r][c] *= (1.0f / 64.0f);

        // online softmax update per row
#pragma unroll
        for (int r = 0; r < 4; r++) {
            float tmax = fmaxf(fmaxf(s[r][0], s[r][1]), fmaxf(s[r][2], s[r][3]));
#pragma unroll
            for (int o = 8; o > 0; o >>= 1)
                tmax = fmaxf(tmax, __shfl_xor_sync(0xffffffffu, tmax, o, 16));
            float newm = fmaxf(m[r], tmax);
            float corr = __expf(m[r] - newm);
            l[r] *= corr;
#pragma unroll
            for (int c = 0; c < 4; c++) acc[r][c] *= corr;
            float psum = 0.0f;
#pragma unroll
            for (int c = 0; c < 4; c++) {
                float p = __expf(s[r][c] - newm);
                s[r][c] = p;
                psum += p;
            }
#pragma unroll
            for (int o = 8; o > 0; o >>= 1)
                psum += __shfl_xor_sync(0xffffffffu, psum, o, 16);
            l[r] += psum;
            m[r] = newm;
        }

        __syncthreads();   // everyone done reading K from kp_s
        // write P into kp_s as [row][col]
#pragma unroll
        for (int r = 0; r < 4; r++)
#pragma unroll
            for (int c = 0; c < 4; c++)
                kp_s[(ty * 4 + r) * 64 + tx * 4 + c] = s[r][c];
        __syncthreads();

        // acc += P @ V
        for (int j = 0; j < 64; j++) {
            float pj[4], vj[4];
#pragma unroll
            for (int r = 0; r < 4; r++) pj[r] = kp_s[(ty * 4 + r) * 64 + j];
#pragma unroll
            for (int c = 0; c < 4; c++) vj[c] = v_s[j * 64 + tx * 4 + c];
#pragma unroll
            for (int r = 0; r < 4; r++)
#pragma unroll
                for (int c = 0; c < 4; c++) acc[r][c] += pj[r] * vj[c];
        }
    }

    // z[b, s, h*64+d] = acc / l
#pragma unroll
    for (int r = 0; r < 4; r++) {
        float inv = 1.0f / l[r];
        int srow = qt * 64 + ty * 4 + r;
        float* zp = g_z + ((size_t)(b * S_ + srow)) * HD_ + h * D_ + tx * 4;
#pragma unroll
        for (int c = 0; c < 4; c++) zp[c] = acc[r][c] * inv;
    }
}

// ---------------------------------------------------------------------------
// K4: logits = relu(z @ lin_w + lin_b)   [4096,1024] x [1024,32000]
// grid = (250, 32), 256 threads, 128x128 tile, BK=8, 8x8 micro-tile
// ---------------------------------------------------------------------------
__global__ void lm_head_kernel(const float* __restrict__ W,
                               const float* __restrict__ bias,
                               float* __restrict__ out) {
    __shared__ float As[8][128];   // [k][row]
    __shared__ float Bs[8][128];   // [k][col]

    int cb = blockIdx.x * 128;
    int rb = blockIdx.y * 128;
    int tid = threadIdx.x, ty = tid >> 4, tx = tid & 15;

    float acc[8][8];
#pragma unroll
    for (int i = 0; i < 8; i++)
#pragma unroll
        for (int j = 0; j < 8; j++) acc[i][j] = 0.0f;

    for (int k0 = 0; k0 < HD_; k0 += 8) {
        {   // A: 128 rows x 8 k, transposed store
            int r = tid >> 1, kq = (tid & 1) << 2;
            float4 av = *reinterpret_cast<const float4*>(
                g_z + (size_t)(rb + r) * HD_ + k0 + kq);
            As[kq + 0][r] = av.x; As[kq + 1][r] = av.y;
            As[kq + 2][r] = av.z; As[kq + 3][r] = av.w;
        }
        {   // B: 8 k x 128 cols
            int kb = tid >> 5, c = (tid & 31) << 2;
            *reinterpret_cast<float4*>(&Bs[kb][c]) =
                *reinterpret_cast<const float4*>(W + (size_t)(k0 + kb) * V_ + cb + c);
        }
        __syncthreads();
#pragma unroll
        for (int k = 0; k < 8; k++) {
            float a[8], bv[8];
#pragma unroll
            for (int i = 0; i < 8; i++) a[i] = As[k][ty * 8 + i];
#pragma unroll
            for (int j = 0; j < 8; j++) bv[j] = Bs[k][tx * 8 + j];
#pragma unroll
            for (int i = 0; i < 8; i++)
#pragma unroll
                for (int j = 0; j < 8; j++) acc[i][j] += a[i] * bv[j];
        }
        __syncthreads();
    }

#pragma unroll
    for (int i = 0; i < 8; i++) {
        int r = rb + ty * 8 + i;
#pragma unroll
        for (int j = 0; j < 8; j++) {
            int c = cb + tx * 8 + j;
            out[(size_t)r * V_ + c] = fmaxf(acc[i][j] + bias[c], 0.0f);
        }
    }
}

// ---------------------------------------------------------------------------
extern "C" void kernel_launch(void* const* d_in, const int* in_sizes, int n_in,
                              void* d_out, int out_size) {
    const int*   x    = (const int*)d_in[0];
    const float* emb  = (const float*)d_in[1];
    const float* pos  = (const float*)d_in[2];
    const float* wq   = (const float*)d_in[3];
    const float* wk   = (const float*)d_in[4];
    const float* wv   = (const float*)d_in[5];
    const float* linw = (const float*)d_in[6];
    const float* linb = (const float*)d_in[7];
    float* out = (float*)d_out;

    embed_gelu_kernel<<<BS_, 256>>>(x, emb, pos);
    qkv_kernel<<<dim3(BS_ / 64, H_, 3), 256>>>(wq, wk, wv);
    attn_kernel<<<dim3(S_ / 64, H_, B_), 256>>>();
    lm_head_kernel<<<dim3(V_ / 128, BS_ / 128), 256>>>(linw, linb, out);
}

// round 5
// speedup vs baseline: 2.3011x; 2.3011x over previous
#include <cuda_runtime.h>
#include <cuda_bf16.h>
#include <math.h>
#include <stdint.h>

// ---------------------------------------------------------------------------
// AttentionLM: embed+pos -> gelu -> per-head QKV proj -> softmax attention
// (buggy /D scaling, no mask) -> concat heads -> lm head (relu(zW+b))
// Shapes: B=2 S=2048 E=1024 H=16 D=64 V=32000
// LM head on mma.sync tf32 (portable sm_80+ PTX: toolchain targets plain
// sm_103, which rejects tcgen05/.cta_group — learned in R4).
// ---------------------------------------------------------------------------

#define B_  2
#define S_  2048
#define E_  1024
#define H_  16
#define D_  64
#define V_  32000
#define BS_ (B_ * S_)          // 4096
#define HD_ (H_ * D_)          // 1024

// scratch (no cudaMalloc allowed)
__device__ float g_h[BS_ * E_];
__device__ float g_q[B_ * H_ * S_ * D_];
__device__ float g_k[B_ * H_ * S_ * D_];
__device__ float g_v[B_ * H_ * S_ * D_];
__device__ float g_z[BS_ * HD_];
__device__ float g_wt[(size_t)V_ * HD_];   // W transposed, tf32-rounded: [V][K]

__device__ __forceinline__ float gelu_erf(float v) {
    return 0.5f * v * (1.0f + erff(v * 0.70710678118654752f));
}

__device__ __forceinline__ float tf32_rna(float x) {
    float r;
    asm("cvt.rna.tf32.f32 %0, %1;" : "=f"(r) : "f"(x));
    return r;
}

__device__ __forceinline__ uint32_t smem_u32(const void* p) {
    uint32_t a;
    asm("{ .reg .u64 t; cvta.to.shared.u64 t, %1; cvt.u32.u64 %0, t; }"
        : "=r"(a) : "l"(p));
    return a;
}

__device__ __forceinline__ void cpa16(uint32_t dst, const float* src) {
    asm volatile("cp.async.cg.shared.global [%0], [%1], 16;"
                 :: "r"(dst), "l"(src) : "memory");
}
#define CP_COMMIT()  asm volatile("cp.async.commit_group;" ::: "memory")
#define CP_WAIT(n)   asm volatile("cp.async.wait_group %0;" :: "n"(n) : "memory")

// ldmatrix x4 (b16 view) — loads one tf32 m16k8 (or two k8n8) fragment set
__device__ __forceinline__ void ldmx4(uint32_t* r, uint32_t addr) {
    asm volatile("ldmatrix.sync.aligned.m8n8.x4.shared.b16 {%0,%1,%2,%3}, [%4];"
        : "=r"(r[0]), "=r"(r[1]), "=r"(r[2]), "=r"(r[3]) : "r"(addr));
}

// D += A * B  (m16n8k8, tf32 in, f32 accum)
__device__ __forceinline__ void mma_tf32(float* d, const uint32_t* a, const uint32_t* b) {
    asm volatile("mma.sync.aligned.m16n8k8.row.col.f32.tf32.tf32.f32 "
        "{%0,%1,%2,%3}, {%4,%5,%6,%7}, {%8,%9}, {%0,%1,%2,%3};"
        : "+f"(d[0]), "+f"(d[1]), "+f"(d[2]), "+f"(d[3])
        : "r"(a[0]), "r"(a[1]), "r"(a[2]), "r"(a[3]), "r"(b[0]), "r"(b[1]));
}

// ---------------------------------------------------------------------------
// K1: h = gelu(embed[x] + pos)
// ---------------------------------------------------------------------------
__global__ void embed_gelu_kernel(const int* __restrict__ x,
                                  const float* __restrict__ emb,
                                  const float* __restrict__ pos) {
    int t = blockIdx.x;
    int s = t & (S_ - 1);
    int row = x[t];
    const float4* e4 = reinterpret_cast<const float4*>(emb + (size_t)row * E_);
    const float4* p4 = reinterpret_cast<const float4*>(pos + (size_t)s * E_);
    float4* h4 = reinterpret_cast<float4*>(g_h + (size_t)t * E_);
    int i = threadIdx.x;
    float4 a = e4[i], b = p4[i], r;
    r.x = gelu_erf(a.x + b.x);
    r.y = gelu_erf(a.y + b.y);
    r.z = gelu_erf(a.z + b.z);
    r.w = gelu_erf(a.w + b.w);
    h4[i] = r;
}

// ---------------------------------------------------------------------------
// K2: QKV projections (SIMT)
// ---------------------------------------------------------------------------
__global__ void qkv_kernel(const float* __restrict__ wq,
                           const float* __restrict__ wk,
                           const float* __restrict__ wv) {
    __shared__ float As[16][64];
    __shared__ float Bs[16][64];

    int rb = blockIdx.x, h = blockIdx.y, proj = blockIdx.z;
    const float* w = (proj == 0 ? wq : proj == 1 ? wk : wv) + (size_t)h * E_ * D_;
    float* outbuf  = (proj == 0 ? g_q : proj == 1 ? g_k : g_v);

    int tid = threadIdx.x, ty = tid >> 4, tx = tid & 15;
    const float* hp = g_h + (size_t)rb * 64 * E_;

    float acc[4][4];
#pragma unroll
    for (int i = 0; i < 4; i++)
#pragma unroll
        for (int j = 0; j < 4; j++) acc[i][j] = 0.0f;

    for (int k0 = 0; k0 < E_; k0 += 16) {
        {
            int r = tid >> 2, kk = (tid & 3) << 2;
            float4 av = *reinterpret_cast<const float4*>(hp + (size_t)r * E_ + k0 + kk);
            As[kk + 0][r] = av.x; As[kk + 1][r] = av.y;
            As[kk + 2][r] = av.z; As[kk + 3][r] = av.w;
        }
        {
            int k = tid >> 4, d4 = (tid & 15) << 2;
            *reinterpret_cast<float4*>(&Bs[k][d4]) =
                *reinterpret_cast<const float4*>(w + (size_t)(k0 + k) * D_ + d4);
        }
        __syncthreads();
#pragma unroll
        for (int k = 0; k < 16; k++) {
            float a[4], bv[4];
#pragma unroll
            for (int i = 0; i < 4; i++) a[i] = As[k][ty * 4 + i];
#pragma unroll
            for (int j = 0; j < 4; j++) bv[j] = Bs[k][tx * 4 + j];
#pragma unroll
            for (int i = 0; i < 4; i++)
#pragma unroll
                for (int j = 0; j < 4; j++) acc[i][j] += a[i] * bv[j];
        }
        __syncthreads();
    }
#pragma unroll
    for (int i = 0; i < 4; i++) {
        int row = rb * 64 + ty * 4 + i;
        int b   = row >> 11;
        int s   = row & (S_ - 1);
        float* op = outbuf + (((size_t)(b * H_ + h) * S_) + s) * D_ + tx * 4;
#pragma unroll
        for (int j = 0; j < 4; j++) op[j] = acc[i][j];
    }
}

// ---------------------------------------------------------------------------
// K3: flash attention (SIMT) — epilogue rounds z to tf32 for the LM head
// ---------------------------------------------------------------------------
__global__ void attn_kernel() {
    __shared__ float q_s[64 * 64];
    __shared__ float kp_s[64 * 64];
    __shared__ float v_s[64 * 64];

    int qt = blockIdx.x, h = blockIdx.y, b = blockIdx.z;
    const float* qp = g_q + (((size_t)(b * H_ + h) * S_) + qt * 64) * D_;
    const float* kp = g_k + ((size_t)(b * H_ + h) * S_) * D_;
    const float* vp = g_v + ((size_t)(b * H_ + h) * S_) * D_;

    int tid = threadIdx.x, ty = tid >> 4, tx = tid & 15;

    for (int i = tid; i < 64 * 64 / 4; i += 256)
        reinterpret_cast<float4*>(q_s)[i] = reinterpret_cast<const float4*>(qp)[i];

    float m[4], l[4], acc[4][4];
#pragma unroll
    for (int r = 0; r < 4; r++) {
        m[r] = -INFINITY; l[r] = 0.0f;
#pragma unroll
        for (int c = 0; c < 4; c++) acc[r][c] = 0.0f;
    }

    for (int kt = 0; kt < S_ / 64; kt++) {
        __syncthreads();
        for (int i = tid; i < 64 * 64; i += 256) {
            int col = i >> 6, d = i & 63;
            kp_s[d * 64 + col] = kp[(size_t)(kt * 64 + col) * D_ + d];
        }
        for (int i = tid; i < 64 * 64 / 4; i += 256)
            reinterpret_cast<float4*>(v_s)[i] =
                reinterpret_cast<const float4*>(vp + (size_t)kt * 64 * D_)[i];
        __syncthreads();

        float s[4][4];
#pragma unroll
        for (int r = 0; r < 4; r++)
#pragma unroll
            for (int c = 0; c < 4; c++) s[r][c] = 0.0f;
        for (int d = 0; d < 64; d++) {
            float a[4], bv[4];
#pragma unroll
            for (int r = 0; r < 4; r++) a[r] = q_s[(ty * 4 + r) * 64 + d];
#pragma unroll
            for (int c = 0; c < 4; c++) bv[c] = kp_s[d * 64 + tx * 4 + c];
#pragma unroll
            for (int r = 0; r < 4; r++)
#pragma unroll
                for (int c = 0; c < 4; c++) s[r][c] += a[r] * bv[c];
        }
#pragma unroll
        for (int r = 0; r < 4; r++)
#pragma unroll
            for (int c = 0; c < 4; c++) s[r][c] *= (1.0f / 64.0f);

#pragma unroll
        for (int r = 0; r < 4; r++) {
            float tmax = fmaxf(fmaxf(s[r][0], s[r][1]), fmaxf(s[r][2], s[r][3]));
#pragma unroll
            for (int o = 8; o > 0; o >>= 1)
                tmax = fmaxf(tmax, __shfl_xor_sync(0xffffffffu, tmax, o, 16));
            float newm = fmaxf(m[r], tmax);
            float corr = __expf(m[r] - newm);
            l[r] *= corr;
#pragma unroll
            for (int c = 0; c < 4; c++) acc[r][c] *= corr;
            float psum = 0.0f;
#pragma unroll
            for (int c = 0; c < 4; c++) {
                float p = __expf(s[r][c] - newm);
                s[r][c] = p;
                psum += p;
            }
#pragma unroll
            for (int o = 8; o > 0; o >>= 1)
                psum += __shfl_xor_sync(0xffffffffu, psum, o, 16);
            l[r] += psum;
            m[r] = newm;
        }

        __syncthreads();
#pragma unroll
        for (int r = 0; r < 4; r++)
#pragma unroll
            for (int c = 0; c < 4; c++)
                kp_s[(ty * 4 + r) * 64 + tx * 4 + c] = s[r][c];
        __syncthreads();

        for (int j = 0; j < 64; j++) {
            float pj[4], vj[4];
#pragma unroll
            for (int r = 0; r < 4; r++) pj[r] = kp_s[(ty * 4 + r) * 64 + j];
#pragma unroll
            for (int c = 0; c < 4; c++) vj[c] = v_s[j * 64 + tx * 4 + c];
#pragma unroll
            for (int r = 0; r < 4; r++)
#pragma unroll
                for (int c = 0; c < 4; c++) acc[r][c] += pj[r] * vj[c];
        }
    }

#pragma unroll
    for (int r = 0; r < 4; r++) {
        float inv = 1.0f / l[r];
        int srow = qt * 64 + ty * 4 + r;
        float* zp = g_z + ((size_t)(b * S_ + srow)) * HD_ + h * D_ + tx * 4;
#pragma unroll
        for (int c = 0; c < 4; c++) zp[c] = tf32_rna(acc[r][c] * inv);
    }
}

// ---------------------------------------------------------------------------
// K4a: W prep — transpose + round to tf32: g_wt[v][k] = tf32(W[k][v])
// ---------------------------------------------------------------------------
__global__ void wt_prep_kernel(const float* __restrict__ W) {
    __shared__ float t[32][33];
    int vb = blockIdx.x * 32, kb = blockIdx.y * 32;
    int tx = threadIdx.x, ty = threadIdx.y;
#pragma unroll
    for (int i = ty; i < 32; i += 8)
        t[i][tx] = tf32_rna(W[(size_t)(kb + i) * V_ + vb + tx]);
    __syncthreads();
#pragma unroll
    for (int i = ty; i < 32; i += 8)
        g_wt[(size_t)(vb + i) * HD_ + kb + tx] = t[tx][i];
}

// ---------------------------------------------------------------------------
// K4b: LM head via mma.sync tf32: out = relu(Z @ W^T(g_wt) + b)
// CTA 128x128, BK=32, 256 thr (warps 2M x 4N, warp tile 64x32),
// 2-stage cp.async pipeline, ldmatrix fragments, padded smem (36 floats/row).
// grid (BS/128=32 fast, V/128=250)
// ---------------------------------------------------------------------------
#define LM_BM 128
#define LM_BN 128
#define LM_BK 32
#define LM_LD 36                          // floats per smem row (144B, ldmatrix conflict-free)
#define LM_STAGE_F (LM_BM * LM_LD)        // 4608 floats per tile
#define LM_SMEM_BYTES (2 * 2 * LM_STAGE_F * 4)   // 73728

__device__ __forceinline__ void lm_load_stage(int ks, uint32_t aA, uint32_t aB,
                                              int rb, int cb, int tid) {
    int k0 = ks * LM_BK;
#pragma unroll
    for (int it = 0; it < 4; it++) {
        int i = tid + it * 256;
        int row = i >> 3, seg = i & 7;
        cpa16(aA + (uint32_t)(row * LM_LD + seg * 4) * 4,
              g_z + (size_t)(rb + row) * HD_ + k0 + seg * 4);
    }
#pragma unroll
    for (int it = 0; it < 4; it++) {
        int i = tid + it * 256;
        int row = i >> 3, seg = i & 7;
        cpa16(aB + (uint32_t)(row * LM_LD + seg * 4) * 4,
              g_wt + (size_t)(cb + row) * HD_ + k0 + seg * 4);
    }
}

__global__ void __launch_bounds__(256)
lm_head_mma_kernel(const float* __restrict__ bias, float* __restrict__ out) {
    extern __shared__ float sm[];
    uint32_t smb = smem_u32(sm);

    int tid = threadIdx.x, lane = tid & 31, wid = tid >> 5;
    int rb = blockIdx.x * LM_BM;
    int cb = blockIdx.y * LM_BN;
    int warp_m = wid & 1, warp_n = wid >> 1;

    // ldmatrix per-lane source rows (8 lanes per 8x8-b16 matrix)
    int lmr = lane & 7, mat = lane >> 3;
    int a_row  = warp_m * 64 + (mat & 1) * 8 + lmr;   // + mt*16
    int a_koff = (mat >> 1) * 4;
    int b_row  = warp_n * 32 + (mat >> 1) * 8 + lmr;  // + ng*16
    int b_koff = (mat & 1) * 4;

    float acc[4][4][4];
#pragma unroll
    for (int mt = 0; mt < 4; mt++)
#pragma unroll
        for (int nt = 0; nt < 4; nt++)
#pragma unroll
            for (int i = 0; i < 4; i++) acc[mt][nt][i] = 0.0f;

    const uint32_t stageB = LM_STAGE_F * 2 * 4;   // bytes per double-tile stage
    lm_load_stage(0, smb, smb + LM_STAGE_F * 4, rb, cb, tid);
    CP_COMMIT();

    const int NS = HD_ / LM_BK;   // 32
    for (int ks = 0; ks < NS; ks++) {
        if (ks + 1 < NS) {
            uint32_t nb = smb + ((ks + 1) & 1) * stageB;
            lm_load_stage(ks + 1, nb, nb + LM_STAGE_F * 4, rb, cb, tid);
            CP_COMMIT();
            CP_WAIT(1);
        } else {
            CP_WAIT(0);
        }
        __syncthreads();

        uint32_t Au = smb + (ks & 1) * stageB;
        uint32_t Bu = Au + LM_STAGE_F * 4;
#pragma unroll
        for (int k8 = 0; k8 < 4; k8++) {
            int k0 = k8 * 8;
            uint32_t af[4][4], bf[2][4];
#pragma unroll
            for (int mt = 0; mt < 4; mt++)
                ldmx4(af[mt], Au + (uint32_t)((a_row + mt * 16) * LM_LD + k0 + a_koff) * 4);
#pragma unroll
            for (int ng = 0; ng < 2; ng++)
                ldmx4(bf[ng], Bu + (uint32_t)((b_row + ng * 16) * LM_LD + k0 + b_koff) * 4);
#pragma unroll
            for (int mt = 0; mt < 4; mt++)
#pragma unroll
                for (int nt = 0; nt < 4; nt++)
                    mma_tf32(acc[mt][nt], af[mt], bf[nt >> 1] + (nt & 1) * 2);
        }
        __syncthreads();
    }

    // epilogue: bias + relu, direct float2 stores from C fragments
    int grp = lane >> 2, qid = lane & 3;
#pragma unroll
    for (int nt = 0; nt < 4; nt++) {
        int col = cb + warp_n * 32 + nt * 8 + qid * 2;
        const float2 bb = *reinterpret_cast<const float2*>(bias + col);
#pragma unroll
        for (int mt = 0; mt < 4; mt++) {
            int r0 = rb + warp_m * 64 + mt * 16 + grp;
            float2 v0, v1;
            v0.x = fmaxf(acc[mt][nt][0] + bb.x, 0.0f);
            v0.y = fmaxf(acc[mt][nt][1] + bb.y, 0.0f);
            v1.x = fmaxf(acc[mt][nt][2] + bb.x, 0.0f);
            v1.y = fmaxf(acc[mt][nt][3] + bb.y, 0.0f);
            *reinterpret_cast<float2*>(out + (size_t)r0 * V_ + col) = v0;
            *reinterpret_cast<float2*>(out + (size_t)(r0 + 8) * V_ + col) = v1;
        }
    }
}

// ---------------------------------------------------------------------------
extern "C" void kernel_launch(void* const* d_in, const int* in_sizes, int n_in,
                              void* d_out, int out_size) {
    const int*   x    = (const int*)d_in[0];
    const float* emb  = (const float*)d_in[1];
    const float* pos  = (const float*)d_in[2];
    const float* wq   = (const float*)d_in[3];
    const float* wk   = (const float*)d_in[4];
    const float* wv   = (const float*)d_in[5];
    const float* linw = (const float*)d_in[6];
    const float* linb = (const float*)d_in[7];
    float* out = (float*)d_out;

    static int smem_set = 0;
    if (!smem_set) {
        cudaFuncSetAttribute(lm_head_mma_kernel,
                             cudaFuncAttributeMaxDynamicSharedMemorySize,
                             LM_SMEM_BYTES);
        smem_set = 1;
    }

    wt_prep_kernel<<<dim3(V_ / 32, HD_ / 32), dim3(32, 8)>>>(linw);
    embed_gelu_kernel<<<BS_, 256>>>(x, emb, pos);
    qkv_kernel<<<dim3(BS_ / 64, H_, 3), 256>>>(wq, wk, wv);
    attn_kernel<<<dim3(S_ / 64, H_, B_), 256>>>();
    lm_head_mma_kernel<<<dim3(BS_ / LM_BM, V_ / LM_BN), 256, LM_SMEM_BYTES>>>(linb, out);
}

// round 6
// speedup vs baseline: 4.1261x; 1.7931x over previous
#include <cuda_runtime.h>
#include <cuda_bf16.h>
#include <math.h>
#include <stdint.h>

// ---------------------------------------------------------------------------
// AttentionLM: embed+pos -> gelu -> per-head QKV proj -> softmax attention
// (buggy /D scaling, no mask) -> concat heads -> lm head (relu(zW+b))
// Shapes: B=2 S=2048 E=1024 H=16 D=64 V=32000
// All three GEMM stages (QKV, attention, LM head) on mma.sync tf32
// (portable sm_80+ PTX — plain sm_103 target rejects tcgen05, learned R4).
// ---------------------------------------------------------------------------

#define B_  2
#define S_  2048
#define E_  1024
#define H_  16
#define D_  64
#define V_  32000
#define BS_ (B_ * S_)          // 4096
#define HD_ (H_ * D_)          // 1024

// scratch (no cudaMalloc allowed)
__device__ float g_h[BS_ * E_];
__device__ float g_q[B_ * H_ * S_ * D_];
__device__ float g_k[B_ * H_ * S_ * D_];
__device__ float g_v[B_ * H_ * S_ * D_];
__device__ float g_z[BS_ * HD_];
__device__ float g_wt[(size_t)V_ * HD_];      // lm W transposed: [V][K]
__device__ float g_wqkv[3 * H_ * D_ * E_];    // packed qkv W: [3*H*D][E]

__device__ __forceinline__ float gelu_erf(float v) {
    return 0.5f * v * (1.0f + erff(v * 0.70710678118654752f));
}
__device__ __forceinline__ float tf32_rna(float x) {
    float r;
    asm("cvt.rna.tf32.f32 %0, %1;" : "=f"(r) : "f"(x));
    return r;
}
__device__ __forceinline__ uint32_t smem_u32(const void* p) {
    uint32_t a;
    asm("{ .reg .u64 t; cvta.to.shared.u64 t, %1; cvt.u32.u64 %0, t; }"
        : "=r"(a) : "l"(p));
    return a;
}
__device__ __forceinline__ void cpa16(uint32_t dst, const float* src) {
    asm volatile("cp.async.cg.shared.global [%0], [%1], 16;"
                 :: "r"(dst), "l"(src) : "memory");
}
#define CP_COMMIT()  asm volatile("cp.async.commit_group;" ::: "memory")
#define CP_WAIT(n)   asm volatile("cp.async.wait_group %0;" :: "n"(n) : "memory")

__device__ __forceinline__ void ldmx4(uint32_t* r, uint32_t addr) {
    asm volatile("ldmatrix.sync.aligned.m8n8.x4.shared.b16 {%0,%1,%2,%3}, [%4];"
        : "=r"(r[0]), "=r"(r[1]), "=r"(r[2]), "=r"(r[3]) : "r"(addr));
}
__device__ __forceinline__ void mma_tf32(float* d, const uint32_t* a, const uint32_t* b) {
    asm volatile("mma.sync.aligned.m16n8k8.row.col.f32.tf32.tf32.f32 "
        "{%0,%1,%2,%3}, {%4,%5,%6,%7}, {%8,%9}, {%0,%1,%2,%3};"
        : "+f"(d[0]), "+f"(d[1]), "+f"(d[2]), "+f"(d[3])
        : "r"(a[0]), "r"(a[1]), "r"(a[2]), "r"(a[3]), "r"(b[0]), "r"(b[1]));
}

// ---------------------------------------------------------------------------
// K1: h = gelu(embed[x] + pos)
// ---------------------------------------------------------------------------
__global__ void embed_gelu_kernel(const int* __restrict__ x,
                                  const float* __restrict__ emb,
                                  const float* __restrict__ pos) {
    int t = blockIdx.x;
    int s = t & (S_ - 1);
    int row = x[t];
    const float4* e4 = reinterpret_cast<const float4*>(emb + (size_t)row * E_);
    const float4* p4 = reinterpret_cast<const float4*>(pos + (size_t)s * E_);
    float4* h4 = reinterpret_cast<float4*>(g_h + (size_t)t * E_);
    int i = threadIdx.x;
    float4 a = e4[i], b = p4[i], r;
    r.x = gelu_erf(a.x + b.x);
    r.y = gelu_erf(a.y + b.y);
    r.z = gelu_erf(a.z + b.z);
    r.w = gelu_erf(a.w + b.w);
    h4[i] = r;
}

// ---------------------------------------------------------------------------
// prep: pack qkv weights -> g_wqkv[(proj*16+h)*64 + d][e]   (n-major, k contig)
// grid (48, E/32, D/32=2), block (32,8)
// ---------------------------------------------------------------------------
__global__ void wqkv_prep_kernel(const float* __restrict__ wq,
                                 const float* __restrict__ wk,
                                 const float* __restrict__ wv) {
    __shared__ float t[32][33];
    int hp = blockIdx.x;
    int eb = blockIdx.y * 32, db = blockIdx.z * 32;
    int proj = hp >> 4, hh = hp & 15;
    const float* w = (proj == 0 ? wq : proj == 1 ? wk : wv) + (size_t)hh * E_ * D_;
    int tx = threadIdx.x, ty = threadIdx.y;
#pragma unroll
    for (int i = ty; i < 32; i += 8)
        t[i][tx] = w[(size_t)(eb + i) * D_ + db + tx];
    __syncthreads();
#pragma unroll
    for (int i = ty; i < 32; i += 8)
        g_wqkv[(size_t)(hp * 64 + db + i) * E_ + eb + tx] = t[tx][i];
}

// ---------------------------------------------------------------------------
// prep: lm W transpose + tf32 round: g_wt[v][k] = tf32(W[k][v])
// ---------------------------------------------------------------------------
__global__ void wt_prep_kernel(const float* __restrict__ W) {
    __shared__ float t[32][33];
    int vb = blockIdx.x * 32, kb = blockIdx.y * 32;
    int tx = threadIdx.x, ty = threadIdx.y;
#pragma unroll
    for (int i = ty; i < 32; i += 8)
        t[i][tx] = tf32_rna(W[(size_t)(kb + i) * V_ + vb + tx]);
    __syncthreads();
#pragma unroll
    for (int i = ty; i < 32; i += 8)
        g_wt[(size_t)(vb + i) * HD_ + kb + tx] = t[tx][i];
}

// ---------------------------------------------------------------------------
// K2: QKV via mma tf32.  CTA 128(M) x 64(N = one head-proj), BK=32.
// grid (BS/128=32, 48), 256 thr, warps 4M x 2N, warp tile 32x32.
// ---------------------------------------------------------------------------
#define QP_LD 36
#define QP_AF (128 * QP_LD)          // 4608
#define QP_BF (64 * QP_LD)           // 2304
#define QP_STAGE (QP_AF + QP_BF)     // 6912
#define QP_SMEM_BYTES (2 * QP_STAGE * 4)   // 55296

__global__ void __launch_bounds__(256)
qkv_mma_kernel() {
    extern __shared__ float sm[];
    uint32_t smb = smem_u32(sm);

    int tid = threadIdx.x, lane = tid & 31, wid = tid >> 5;
    int rb = blockIdx.x * 128;
    int hp = blockIdx.y;
    int warp_m = wid & 3, warp_n = wid >> 2;

    int lmr = lane & 7, mat = lane >> 3;
    int grp = lane >> 2, qid = lane & 3;
    int a_row  = warp_m * 32 + (mat & 1) * 8 + lmr;
    int a_koff = (mat >> 1) * 4;
    int b_row  = warp_n * 32 + (mat >> 1) * 8 + lmr;
    int b_koff = (mat & 1) * 4;

    const float* Bsrc = g_wqkv + (size_t)hp * 64 * E_;

    float acc[2][4][4];
#pragma unroll
    for (int mt = 0; mt < 2; mt++)
#pragma unroll
        for (int nt = 0; nt < 4; nt++)
#pragma unroll
            for (int i = 0; i < 4; i++) acc[mt][nt][i] = 0.0f;

    // stage loader
    auto load_stage = [&](int ks, uint32_t base) {
        int k0 = ks * 32;
        uint32_t aB = base, bB = base + QP_AF * 4;
#pragma unroll
        for (int it = 0; it < 4; it++) {
            int i = tid + it * 256;
            int row = i >> 3, seg = i & 7;
            cpa16(aB + (uint32_t)(row * QP_LD + seg * 4) * 4,
                  g_h + (size_t)(rb + row) * E_ + k0 + seg * 4);
        }
#pragma unroll
        for (int it = 0; it < 2; it++) {
            int i = tid + it * 256;
            int row = i >> 3, seg = i & 7;
            cpa16(bB + (uint32_t)(row * QP_LD + seg * 4) * 4,
                  Bsrc + (size_t)row * E_ + k0 + seg * 4);
        }
    };

    load_stage(0, smb);
    CP_COMMIT();

    const int NS = E_ / 32;   // 32
    for (int ks = 0; ks < NS; ks++) {
        if (ks + 1 < NS) {
            load_stage(ks + 1, smb + ((ks + 1) & 1) * QP_STAGE * 4);
            CP_COMMIT();
            CP_WAIT(1);
        } else {
            CP_WAIT(0);
        }
        __syncthreads();

        uint32_t Au = smb + (ks & 1) * QP_STAGE * 4;
        uint32_t Bu = Au + QP_AF * 4;
#pragma unroll
        for (int k8 = 0; k8 < 4; k8++) {
            int k0 = k8 * 8;
            uint32_t af[2][4], bf[2][4];
#pragma unroll
            for (int mt = 0; mt < 2; mt++)
                ldmx4(af[mt], Au + (uint32_t)((a_row + mt * 16) * QP_LD + k0 + a_koff) * 4);
#pragma unroll
            for (int ng = 0; ng < 2; ng++)
                ldmx4(bf[ng], Bu + (uint32_t)((b_row + ng * 16) * QP_LD + k0 + b_koff) * 4);
#pragma unroll
            for (int mt = 0; mt < 2; mt++)
#pragma unroll
                for (int nt = 0; nt < 4; nt++)
                    mma_tf32(acc[mt][nt], af[mt], bf[nt >> 1] + (nt & 1) * 2);
        }
        __syncthreads();
    }

    // epilogue -> q/k/v[b,h,s,d]
    int proj = hp >> 4, hh = hp & 15;
    float* outb = (proj == 0 ? g_q : proj == 1 ? g_k : g_v);
#pragma unroll
    for (int mt = 0; mt < 2; mt++) {
        int row = rb + warp_m * 32 + mt * 16 + grp;
        int bsel = row >> 11, s = row & (S_ - 1);
        float* p0 = outb + ((size_t)(bsel * H_ + hh) * S_ + s) * D_;
        float* p1 = p0 + 8 * D_;
#pragma unroll
        for (int nt = 0; nt < 4; nt++) {
            int col = warp_n * 32 + nt * 8 + 2 * qid;
            float2 v0 = { acc[mt][nt][0], acc[mt][nt][1] };
            float2 v1 = { acc[mt][nt][2], acc[mt][nt][3] };
            *reinterpret_cast<float2*>(p0 + col) = v0;
            *reinterpret_cast<float2*>(p1 + col) = v1;
        }
    }
}

// ---------------------------------------------------------------------------
// K3: flash attention on mma tf32.
// CTA: 128 q-rows x one (b,h); 8 warps x 16 rows. K/V tiles of 64, double buf.
// scores/64 (faithful buggy double scale). grid (16, H, B), 256 thr.
// ---------------------------------------------------------------------------
#define AT_LD 68
#define AT_Q   0                      // 128*68 = 8704
#define AT_K0  8704                   // 2 x 64*68
#define AT_V0  17408                  // 2 x 64*68 (Vst staging)
#define AT_VT  26112                  // 64*68 (V transposed)
#define AT_PW  30464                  // 8 x 16*68
#define AT_TOT 39168
#define AT_SMEM_BYTES (AT_TOT * 4)    // 156672

__global__ void attn_mma_kernel() {
    extern __shared__ float sm[];
    uint32_t smb = smem_u32(sm);

    int tid = threadIdx.x, lane = tid & 31, wid = tid >> 5;
    int qt = blockIdx.x, h = blockIdx.y, b = blockIdx.z;
    int bh = b * H_ + h;
    const float* qp = g_q + ((size_t)bh * S_ + qt * 128) * D_;
    const float* kp = g_k + (size_t)bh * S_ * D_;
    const float* vp = g_v + (size_t)bh * S_ * D_;

    int lmr = lane & 7, mat = lane >> 3;
    int grp = lane >> 2, qid = lane & 3;
    int a_row  = (mat & 1) * 8 + lmr;     // warp-local A rows
    int a_koff = (mat >> 1) * 4;
    int b_row  = (mat >> 1) * 8 + lmr;
    int b_koff = (mat & 1) * 4;

    // preload K/V tile 0
#pragma unroll
    for (int it = 0; it < 4; it++) {
        int i = tid + it * 256;
        int row = i >> 4, seg = i & 15;
        cpa16(smb + (uint32_t)(AT_K0 + row * AT_LD + seg * 4) * 4, kp + row * 64 + seg * 4);
        cpa16(smb + (uint32_t)(AT_V0 + row * AT_LD + seg * 4) * 4, vp + row * 64 + seg * 4);
    }
    CP_COMMIT();

    // load Q tile
#pragma unroll
    for (int it = 0; it < 8; it++) {
        int i = tid + it * 256;
        int row = i >> 4, seg = i & 15;
        *reinterpret_cast<float4*>(sm + AT_Q + row * AT_LD + seg * 4) =
            *reinterpret_cast<const float4*>(qp + (size_t)row * 64 + seg * 4);
    }
    __syncthreads();

    // Q fragments held in registers for the whole kernel
    uint32_t qf[8][4];
#pragma unroll
    for (int k8 = 0; k8 < 8; k8++)
        ldmx4(qf[k8], smb + (uint32_t)(AT_Q + (wid * 16 + a_row) * AT_LD + k8 * 8 + a_koff) * 4);

    float m0 = -INFINITY, m1 = -INFINITY, l0 = 0.0f, l1 = 0.0f;
    float zacc[8][4];
#pragma unroll
    for (int jb = 0; jb < 8; jb++)
#pragma unroll
        for (int i = 0; i < 4; i++) zacc[jb][i] = 0.0f;

    uint32_t PwB = smb + (uint32_t)(AT_PW + wid * 16 * AT_LD) * 4;

    for (int kt = 0; kt < S_ / 64; kt++) {
        int buf = kt & 1;
        uint32_t ksb = smb + (uint32_t)(AT_K0 + buf * 4352) * 4;
        int vsf = AT_V0 + buf * 4352;

        CP_WAIT(0);
        __syncthreads();                     // buf ready; all warps past last tile

        if (kt + 1 < S_ / 64) {              // prefetch next tile into buf^1
            const float* kb = kp + (size_t)(kt + 1) * 64 * D_;
            const float* vb = vp + (size_t)(kt + 1) * 64 * D_;
            uint32_t kd = smb + (uint32_t)(AT_K0 + (buf ^ 1) * 4352) * 4;
            uint32_t vd = smb + (uint32_t)(AT_V0 + (buf ^ 1) * 4352) * 4;
#pragma unroll
            for (int it = 0; it < 4; it++) {
                int i = tid + it * 256;
                int row = i >> 4, seg = i & 15;
                cpa16(kd + (uint32_t)(row * AT_LD + seg * 4) * 4, kb + row * 64 + seg * 4);
                cpa16(vd + (uint32_t)(row * AT_LD + seg * 4) * 4, vb + row * 64 + seg * 4);
            }
            CP_COMMIT();
        }

        // transpose V tile: Vts[d][t] = Vst[t][d]
#pragma unroll
        for (int it = 0; it < 16; it++) {
            int i = tid + it * 256;
            int d = i >> 6, t = i & 63;
            sm[AT_VT + d * AT_LD + t] = sm[vsf + t * AT_LD + d];
        }
        __syncthreads();

        // S = Q K^T / 64
        float sacc[8][4];
#pragma unroll
        for (int jb = 0; jb < 8; jb++)
#pragma unroll
            for (int i = 0; i < 4; i++) sacc[jb][i] = 0.0f;
#pragma unroll
        for (int k8 = 0; k8 < 8; k8++) {
            uint32_t bf[4][4];
#pragma unroll
            for (int nb = 0; nb < 4; nb++)
                ldmx4(bf[nb], ksb + (uint32_t)((nb * 16 + b_row) * AT_LD + k8 * 8 + b_koff) * 4);
#pragma unroll
            for (int nb = 0; nb < 4; nb++) {
                mma_tf32(sacc[nb * 2],     qf[k8], bf[nb]);
                mma_tf32(sacc[nb * 2 + 1], qf[k8], bf[nb] + 2);
            }
        }
#pragma unroll
        for (int jb = 0; jb < 8; jb++)
#pragma unroll
            for (int i = 0; i < 4; i++) sacc[jb][i] *= (1.0f / 64.0f);

        // online softmax (rows grp / grp+8, reduce over qid lanes)
        float t0 = -INFINITY, t1 = -INFINITY;
#pragma unroll
        for (int jb = 0; jb < 8; jb++) {
            t0 = fmaxf(t0, fmaxf(sacc[jb][0], sacc[jb][1]));
            t1 = fmaxf(t1, fmaxf(sacc[jb][2], sacc[jb][3]));
        }
#pragma unroll
        for (int o = 1; o <= 2; o <<= 1) {
            t0 = fmaxf(t0, __shfl_xor_sync(0xffffffffu, t0, o));
            t1 = fmaxf(t1, __shfl_xor_sync(0xffffffffu, t1, o));
        }
        float nm0 = fmaxf(m0, t0), nm1 = fmaxf(m1, t1);
        float c0 = __expf(m0 - nm0), c1 = __expf(m1 - nm1);
        l0 *= c0; l1 *= c1;
#pragma unroll
        for (int jb = 0; jb < 8; jb++) {
            zacc[jb][0] *= c0; zacc[jb][1] *= c0;
            zacc[jb][2] *= c1; zacc[jb][3] *= c1;
        }
        float ps0 = 0.0f, ps1 = 0.0f;
#pragma unroll
        for (int jb = 0; jb < 8; jb++) {
            float p;
            p = __expf(sacc[jb][0] - nm0); sacc[jb][0] = p; ps0 += p;
            p = __expf(sacc[jb][1] - nm0); sacc[jb][1] = p; ps0 += p;
            p = __expf(sacc[jb][2] - nm1); sacc[jb][2] = p; ps1 += p;
            p = __expf(sacc[jb][3] - nm1); sacc[jb][3] = p; ps1 += p;
        }
#pragma unroll
        for (int o = 1; o <= 2; o <<= 1) {
            ps0 += __shfl_xor_sync(0xffffffffu, ps0, o);
            ps1 += __shfl_xor_sync(0xffffffffu, ps1, o);
        }
        l0 += ps0; l1 += ps1; m0 = nm0; m1 = nm1;

        // stage P in warp-private smem (C-frag -> A-frag conversion)
        float* Pf = sm + AT_PW + wid * 16 * AT_LD;
#pragma unroll
        for (int jb = 0; jb < 8; jb++) {
            int col = jb * 8 + 2 * qid;
            float2 u0 = { sacc[jb][0], sacc[jb][1] };
            float2 u1 = { sacc[jb][2], sacc[jb][3] };
            *reinterpret_cast<float2*>(Pf + grp * AT_LD + col) = u0;
            *reinterpret_cast<float2*>(Pf + (grp + 8) * AT_LD + col) = u1;
        }
        __syncwarp();

        // Z += P V
#pragma unroll
        for (int t8 = 0; t8 < 8; t8++) {
            uint32_t pa[4];
            ldmx4(pa, PwB + (uint32_t)(a_row * AT_LD + t8 * 8 + a_koff) * 4);
            uint32_t vf[4][4];
#pragma unroll
            for (int nb = 0; nb < 4; nb++)
                ldmx4(vf[nb], smb + (uint32_t)(AT_VT + (nb * 16 + b_row) * AT_LD + t8 * 8 + b_koff) * 4);
#pragma unroll
            for (int nb = 0; nb < 4; nb++) {
                mma_tf32(zacc[nb * 2],     pa, vf[nb]);
                mma_tf32(zacc[nb * 2 + 1], pa, vf[nb] + 2);
            }
        }
    }

    // epilogue: z / l, tf32-rounded for the LM head, layout g_z[b,s,h*64+d]
    float i0 = 1.0f / l0, i1 = 1.0f / l1;
    int s0 = qt * 128 + wid * 16 + grp;
    float* z0 = g_z + ((size_t)(b * S_ + s0)) * HD_ + h * D_;
    float* z1 = z0 + (size_t)8 * HD_;
#pragma unroll
    for (int jb = 0; jb < 8; jb++) {
        int col = jb * 8 + 2 * qid;
        float2 w0 = { tf32_rna(zacc[jb][0] * i0), tf32_rna(zacc[jb][1] * i0) };
        float2 w1 = { tf32_rna(zacc[jb][2] * i1), tf32_rna(zacc[jb][3] * i1) };
        *reinterpret_cast<float2*>(z0 + col) = w0;
        *reinterpret_cast<float2*>(z1 + col) = w1;
    }
}

// ---------------------------------------------------------------------------
// K4: LM head via mma.sync tf32 (unchanged from R5 — passed at rel_err 2.8e-6)
// ---------------------------------------------------------------------------
#define LM_BM 128
#define LM_BN 128
#define LM_BK 32
#define LM_LD 36
#define LM_STAGE_F (LM_BM * LM_LD)
#define LM_SMEM_BYTES (2 * 2 * LM_STAGE_F * 4)   // 73728

__device__ __forceinline__ void lm_load_stage(int ks, uint32_t aA, uint32_t aB,
                                              int rb, int cb, int tid) {
    int k0 = ks * LM_BK;
#pragma unroll
    for (int it = 0; it < 4; it++) {
        int i = tid + it * 256;
        int row = i >> 3, seg = i & 7;
        cpa16(aA + (uint32_t)(row * LM_LD + seg * 4) * 4,
              g_z + (size_t)(rb + row) * HD_ + k0 + seg * 4);
    }
#pragma unroll
    for (int it = 0; it < 4; it++) {
        int i = tid + it * 256;
        int row = i >> 3, seg = i & 7;
        cpa16(aB + (uint32_t)(row * LM_LD + seg * 4) * 4,
              g_wt + (size_t)(cb + row) * HD_ + k0 + seg * 4);
    }
}

__global__ void __launch_bounds__(256)
lm_head_mma_kernel(const float* __restrict__ bias, float* __restrict__ out) {
    extern __shared__ float sm[];
    uint32_t smb = smem_u32(sm);

    int tid = threadIdx.x, lane = tid & 31, wid = tid >> 5;
    int rb = blockIdx.x * LM_BM;
    int cb = blockIdx.y * LM_BN;
    int warp_m = wid & 1, warp_n = wid >> 1;

    int lmr = lane & 7, mat = lane >> 3;
    int a_row  = warp_m * 64 + (mat & 1) * 8 + lmr;
    int a_koff = (mat >> 1) * 4;
    int b_row  = warp_n * 32 + (mat >> 1) * 8 + lmr;
    int b_koff = (mat & 1) * 4;

    float acc[4][4][4];
#pragma unroll
    for (int mt = 0; mt < 4; mt++)
#pragma unroll
        for (int nt = 0; nt < 4; nt++)
#pragma unroll
            for (int i = 0; i < 4; i++) acc[mt][nt][i] = 0.0f;

    const uint32_t stageB = LM_STAGE_F * 2 * 4;
    lm_load_stage(0, smb, smb + LM_STAGE_F * 4, rb, cb, tid);
    CP_COMMIT();

    const int NS = HD_ / LM_BK;
    for (int ks = 0; ks < NS; ks++) {
        if (ks + 1 < NS) {
            uint32_t nb = smb + ((ks + 1) & 1) * stageB;
            lm_load_stage(ks + 1, nb, nb + LM_STAGE_F * 4, rb, cb, tid);
            CP_COMMIT();
            CP_WAIT(1);
        } else {
            CP_WAIT(0);
        }
        __syncthreads();

        uint32_t Au = smb + (ks & 1) * stageB;
        uint32_t Bu = Au + LM_STAGE_F * 4;
#pragma unroll
        for (int k8 = 0; k8 < 4; k8++) {
            int k0 = k8 * 8;
            uint32_t af[4][4], bf[2][4];
#pragma unroll
            for (int mt = 0; mt < 4; mt++)
                ldmx4(af[mt], Au + (uint32_t)((a_row + mt * 16) * LM_LD + k0 + a_koff) * 4);
#pragma unroll
            for (int ng = 0; ng < 2; ng++)
                ldmx4(bf[ng], Bu + (uint32_t)((b_row + ng * 16) * LM_LD + k0 + b_koff) * 4);
#pragma unroll
            for (int mt = 0; mt < 4; mt++)
#pragma unroll
                for (int nt = 0; nt < 4; nt++)
                    mma_tf32(acc[mt][nt], af[mt], bf[nt >> 1] + (nt & 1) * 2);
        }
        __syncthreads();
    }

    int grp = lane >> 2, qid = lane & 3;
#pragma unroll
    for (int nt = 0; nt < 4; nt++) {
        int col = cb + warp_n * 32 + nt * 8 + qid * 2;
        const float2 bb = *reinterpret_cast<const float2*>(bias + col);
#pragma unroll
        for (int mt = 0; mt < 4; mt++) {
            int r0 = rb + warp_m * 64 + mt * 16 + grp;
            float2 v0, v1;
            v0.x = fmaxf(acc[mt][nt][0] + bb.x, 0.0f);
            v0.y = fmaxf(acc[mt][nt][1] + bb.y, 0.0f);
            v1.x = fmaxf(acc[mt][nt][2] + bb.x, 0.0f);
            v1.y = fmaxf(acc[mt][nt][3] + bb.y, 0.0f);
            *reinterpret_cast<float2*>(out + (size_t)r0 * V_ + col) = v0;
            *reinterpret_cast<float2*>(out + (size_t)(r0 + 8) * V_ + col) = v1;
        }
    }
}

// ---------------------------------------------------------------------------
extern "C" void kernel_launch(void* const* d_in, const int* in_sizes, int n_in,
                              void* d_out, int out_size) {
    const int*   x    = (const int*)d_in[0];
    const float* emb  = (const float*)d_in[1];
    const float* pos  = (const float*)d_in[2];
    const float* wq   = (const float*)d_in[3];
    const float* wk   = (const float*)d_in[4];
    const float* wv   = (const float*)d_in[5];
    const float* linw = (const float*)d_in[6];
    const float* linb = (const float*)d_in[7];
    float* out = (float*)d_out;

    static int smem_set = 0;
    if (!smem_set) {
        cudaFuncSetAttribute(lm_head_mma_kernel,
                             cudaFuncAttributeMaxDynamicSharedMemorySize, LM_SMEM_BYTES);
        cudaFuncSetAttribute(qkv_mma_kernel,
                             cudaFuncAttributeMaxDynamicSharedMemorySize, QP_SMEM_BYTES);
        cudaFuncSetAttribute(attn_mma_kernel,
                             cudaFuncAttributeMaxDynamicSharedMemorySize, AT_SMEM_BYTES);
        smem_set = 1;
    }

    wqkv_prep_kernel<<<dim3(48, E_ / 32, D_ / 32), dim3(32, 8)>>>(wq, wk, wv);
    wt_prep_kernel<<<dim3(V_ / 32, HD_ / 32), dim3(32, 8)>>>(linw);
    embed_gelu_kernel<<<BS_, 256>>>(x, emb, pos);
    qkv_mma_kernel<<<dim3(BS_ / 128, 48), 256, QP_SMEM_BYTES>>>();
    attn_mma_kernel<<<dim3(S_ / 128, H_, B_), 256, AT_SMEM_BYTES>>>();
    lm_head_mma_kernel<<<dim3(BS_ / LM_BM, V_ / LM_BN), 256, LM_SMEM_BYTES>>>(linb, out);
}

// round 8
// speedup vs baseline: 6.2071x; 1.5043x over previous
#include <cuda_runtime.h>
#include <cuda_fp16.h>
#include <math.h>
#include <stdint.h>

// ---------------------------------------------------------------------------
// AttentionLM: embed+pos -> gelu -> per-head QKV proj -> softmax attention
// (buggy /D scaling, no mask) -> concat heads -> lm head (relu(zW+b))
// Shapes: B=2 S=2048 E=1024 H=16 D=64 V=32000
// QKV + attention: mma.sync tf32.  LM head: mma.sync fp16 m16n8k16 (f32 acc).
// (plain sm_103 ptxas target rejects tcgen05 — learned R4)
// ---------------------------------------------------------------------------

#define B_  2
#define S_  2048
#define E_  1024
#define H_  16
#define D_  64
#define V_  32000
#define BS_ (B_ * S_)          // 4096
#define HD_ (H_ * D_)          // 1024

// scratch (no cudaMalloc allowed)
__device__ float  g_h[BS_ * E_];
__device__ float  g_q[B_ * H_ * S_ * D_];
__device__ float  g_k[B_ * H_ * S_ * D_];
__device__ float  g_v[B_ * H_ * S_ * D_];
__device__ __half g_zh[BS_ * HD_];            // attention output, fp16
__device__ __half g_wth[(size_t)V_ * HD_];    // lm W transposed fp16: [V][K]
__device__ float  g_wqkv[3 * H_ * D_ * E_];   // packed qkv W: [3*H*D][E]

__device__ __forceinline__ float gelu_erf(float v) {
    return 0.5f * v * (1.0f + erff(v * 0.70710678118654752f));
}
__device__ __forceinline__ uint32_t smem_u32(const void* p) {
    uint32_t a;
    asm("{ .reg .u64 t; cvta.to.shared.u64 t, %1; cvt.u32.u64 %0, t; }"
        : "=r"(a) : "l"(p));
    return a;
}
__device__ __forceinline__ void cpa16(uint32_t dst, const void* src) {
    asm volatile("cp.async.cg.shared.global [%0], [%1], 16;"
                 :: "r"(dst), "l"(src) : "memory");
}
#define CP_COMMIT()  asm volatile("cp.async.commit_group;" ::: "memory")
#define CP_WAIT(n)   asm volatile("cp.async.wait_group %0;" :: "n"(n) : "memory")

__device__ __forceinline__ void ldmx4(uint32_t* r, uint32_t addr) {
    asm volatile("ldmatrix.sync.aligned.m8n8.x4.shared.b16 {%0,%1,%2,%3}, [%4];"
        : "=r"(r[0]), "=r"(r[1]), "=r"(r[2]), "=r"(r[3]) : "r"(addr));
}
__device__ __forceinline__ void mma_tf32(float* d, const uint32_t* a, const uint32_t* b) {
    asm volatile("mma.sync.aligned.m16n8k8.row.col.f32.tf32.tf32.f32 "
        "{%0,%1,%2,%3}, {%4,%5,%6,%7}, {%8,%9}, {%0,%1,%2,%3};"
        : "+f"(d[0]), "+f"(d[1]), "+f"(d[2]), "+f"(d[3])
        : "r"(a[0]), "r"(a[1]), "r"(a[2]), "r"(a[3]), "r"(b[0]), "r"(b[1]));
}
__device__ __forceinline__ void mma_f16(float* d, const uint32_t* a, const uint32_t* b) {
    asm volatile("mma.sync.aligned.m16n8k16.row.col.f32.f16.f16.f32 "
        "{%0,%1,%2,%3}, {%4,%5,%6,%7}, {%8,%9}, {%0,%1,%2,%3};"
        : "+f"(d[0]), "+f"(d[1]), "+f"(d[2]), "+f"(d[3])
        : "r"(a[0]), "r"(a[1]), "r"(a[2]), "r"(a[3]), "r"(b[0]), "r"(b[1]));
}

// ---------------------------------------------------------------------------
// K1: h = gelu(embed[x] + pos)
// ---------------------------------------------------------------------------
__global__ void embed_gelu_kernel(const int* __restrict__ x,
                                  const float* __restrict__ emb,
                                  const float* __restrict__ pos) {
    int t = blockIdx.x;
    int s = t & (S_ - 1);
    int row = x[t];
    const float4* e4 = reinterpret_cast<const float4*>(emb + (size_t)row * E_);
    const float4* p4 = reinterpret_cast<const float4*>(pos + (size_t)s * E_);
    float4* h4 = reinterpret_cast<float4*>(g_h + (size_t)t * E_);
    int i = threadIdx.x;
    float4 a = e4[i], b = p4[i], r;
    r.x = gelu_erf(a.x + b.x);
    r.y = gelu_erf(a.y + b.y);
    r.z = gelu_erf(a.z + b.z);
    r.w = gelu_erf(a.w + b.w);
    h4[i] = r;
}

// ---------------------------------------------------------------------------
// prep: pack qkv weights -> g_wqkv[(proj*16+h)*64 + d][e]
// ---------------------------------------------------------------------------
__global__ void wqkv_prep_kernel(const float* __restrict__ wq,
                                 const float* __restrict__ wk,
                                 const float* __restrict__ wv) {
    __shared__ float t[32][33];
    int hp = blockIdx.x;
    int eb = blockIdx.y * 32, db = blockIdx.z * 32;
    int proj = hp >> 4, hh = hp & 15;
    const float* w = (proj == 0 ? wq : proj == 1 ? wk : wv) + (size_t)hh * E_ * D_;
    int tx = threadIdx.x, ty = threadIdx.y;
#pragma unroll
    for (int i = ty; i < 32; i += 8)
        t[i][tx] = w[(size_t)(eb + i) * D_ + db + tx];
    __syncthreads();
#pragma unroll
    for (int i = ty; i < 32; i += 8)
        g_wqkv[(size_t)(hp * 64 + db + i) * E_ + eb + tx] = t[tx][i];
}

// ---------------------------------------------------------------------------
// prep: lm W transpose -> fp16: g_wth[v][k] = half(W[k][v])
// ---------------------------------------------------------------------------
__global__ void wt_prep_kernel(const float* __restrict__ W) {
    __shared__ float t[32][33];
    int vb = blockIdx.x * 32, kb = blockIdx.y * 32;
    int tx = threadIdx.x, ty = threadIdx.y;
#pragma unroll
    for (int i = ty; i < 32; i += 8)
        t[i][tx] = W[(size_t)(kb + i) * V_ + vb + tx];
    __syncthreads();
#pragma unroll
    for (int i = ty; i < 32; i += 8)
        g_wth[(size_t)(vb + i) * HD_ + kb + tx] = __float2half(t[tx][i]);
}

// ---------------------------------------------------------------------------
// K2: QKV via mma tf32.  CTA 128(M) x 64(N = one head-proj), BK=32.
// ---------------------------------------------------------------------------
#define QP_LD 36
#define QP_AF (128 * QP_LD)
#define QP_BF (64 * QP_LD)
#define QP_STAGE (QP_AF + QP_BF)
#define QP_SMEM_BYTES (2 * QP_STAGE * 4)   // 55296

__global__ void __launch_bounds__(256)
qkv_mma_kernel() {
    extern __shared__ float sm[];
    uint32_t smb = smem_u32(sm);

    int tid = threadIdx.x, lane = tid & 31, wid = tid >> 5;
    int rb = blockIdx.x * 128;
    int hp = blockIdx.y;
    int warp_m = wid & 3, warp_n = wid >> 2;

    int lmr = lane & 7, mat = lane >> 3;
    int grp = lane >> 2, qid = lane & 3;
    int a_row  = warp_m * 32 + (mat & 1) * 8 + lmr;
    int a_koff = (mat >> 1) * 4;
    int b_row  = warp_n * 32 + (mat >> 1) * 8 + lmr;
    int b_koff = (mat & 1) * 4;

    const float* Bsrc = g_wqkv + (size_t)hp * 64 * E_;

    float acc[2][4][4];
#pragma unroll
    for (int mt = 0; mt < 2; mt++)
#pragma unroll
        for (int nt = 0; nt < 4; nt++)
#pragma unroll
            for (int i = 0; i < 4; i++) acc[mt][nt][i] = 0.0f;

    auto load_stage = [&](int ks, uint32_t base) {
        int k0 = ks * 32;
        uint32_t aB = base, bB = base + QP_AF * 4;
#pragma unroll
        for (int it = 0; it < 4; it++) {
            int i = tid + it * 256;
            int row = i >> 3, seg = i & 7;
            cpa16(aB + (uint32_t)(row * QP_LD + seg * 4) * 4,
                  g_h + (size_t)(rb + row) * E_ + k0 + seg * 4);
        }
#pragma unroll
        for (int it = 0; it < 2; it++) {
            int i = tid + it * 256;
            int row = i >> 3, seg = i & 7;
            cpa16(bB + (uint32_t)(row * QP_LD + seg * 4) * 4,
                  Bsrc + (size_t)row * E_ + k0 + seg * 4);
        }
    };

    load_stage(0, smb);
    CP_COMMIT();

    const int NS = E_ / 32;
    for (int ks = 0; ks < NS; ks++) {
        if (ks + 1 < NS) {
            load_stage(ks + 1, smb + ((ks + 1) & 1) * QP_STAGE * 4);
            CP_COMMIT();
            CP_WAIT(1);
        } else {
            CP_WAIT(0);
        }
        __syncthreads();

        uint32_t Au = smb + (ks & 1) * QP_STAGE * 4;
        uint32_t Bu = Au + QP_AF * 4;
#pragma unroll
        for (int k8 = 0; k8 < 4; k8++) {
            int k0 = k8 * 8;
            uint32_t af[2][4], bf[2][4];
#pragma unroll
            for (int mt = 0; mt < 2; mt++)
                ldmx4(af[mt], Au + (uint32_t)((a_row + mt * 16) * QP_LD + k0 + a_koff) * 4);
#pragma unroll
            for (int ng = 0; ng < 2; ng++)
                ldmx4(bf[ng], Bu + (uint32_t)((b_row + ng * 16) * QP_LD + k0 + b_koff) * 4);
#pragma unroll
            for (int mt = 0; mt < 2; mt++)
#pragma unroll
                for (int nt = 0; nt < 4; nt++)
                    mma_tf32(acc[mt][nt], af[mt], bf[nt >> 1] + (nt & 1) * 2);
        }
        __syncthreads();
    }

    int proj = hp >> 4, hh = hp & 15;
    float* outb = (proj == 0 ? g_q : proj == 1 ? g_k : g_v);
#pragma unroll
    for (int mt = 0; mt < 2; mt++) {
        int row = rb + warp_m * 32 + mt * 16 + grp;
        int bsel = row >> 11, s = row & (S_ - 1);
        float* p0 = outb + ((size_t)(bsel * H_ + hh) * S_ + s) * D_;
        float* p1 = p0 + 8 * D_;
#pragma unroll
        for (int nt = 0; nt < 4; nt++) {
            int col = warp_n * 32 + nt * 8 + 2 * qid;
            float2 v0 = { acc[mt][nt][0], acc[mt][nt][1] };
            float2 v1 = { acc[mt][nt][2], acc[mt][nt][3] };
            *reinterpret_cast<float2*>(p0 + col) = v0;
            *reinterpret_cast<float2*>(p1 + col) = v1;
        }
    }
}

// ---------------------------------------------------------------------------
// K3: flash attention on mma tf32 (epilogue writes fp16 g_zh).
// ---------------------------------------------------------------------------
#define AT_LD 68
#define AT_Q   0
#define AT_K0  8704
#define AT_V0  17408
#define AT_VT  26112
#define AT_PW  30464
#define AT_TOT 39168
#define AT_SMEM_BYTES (AT_TOT * 4)    // 156672

__global__ void attn_mma_kernel() {
    extern __shared__ float sm[];
    uint32_t smb = smem_u32(sm);

    int tid = threadIdx.x, lane = tid & 31, wid = tid >> 5;
    int qt = blockIdx.x, h = blockIdx.y, b = blockIdx.z;
    int bh = b * H_ + h;
    const float* qp = g_q + ((size_t)bh * S_ + qt * 128) * D_;
    const float* kp = g_k + (size_t)bh * S_ * D_;
    const float* vp = g_v + (size_t)bh * S_ * D_;

    int lmr = lane & 7, mat = lane >> 3;
    int grp = lane >> 2, qid = lane & 3;
    int a_row  = (mat & 1) * 8 + lmr;
    int a_koff = (mat >> 1) * 4;
    int b_row  = (mat >> 1) * 8 + lmr;
    int b_koff = (mat & 1) * 4;

#pragma unroll
    for (int it = 0; it < 4; it++) {
        int i = tid + it * 256;
        int row = i >> 4, seg = i & 15;
        cpa16(smb + (uint32_t)(AT_K0 + row * AT_LD + seg * 4) * 4, kp + row * 64 + seg * 4);
        cpa16(smb + (uint32_t)(AT_V0 + row * AT_LD + seg * 4) * 4, vp + row * 64 + seg * 4);
    }
    CP_COMMIT();

#pragma unroll
    for (int it = 0; it < 8; it++) {
        int i = tid + it * 256;
        int row = i >> 4, seg = i & 15;
        *reinterpret_cast<float4*>(sm + AT_Q + row * AT_LD + seg * 4) =
            *reinterpret_cast<const float4*>(qp + (size_t)row * 64 + seg * 4);
    }
    __syncthreads();

    uint32_t qf[8][4];
#pragma unroll
    for (int k8 = 0; k8 < 8; k8++)
        ldmx4(qf[k8], smb + (uint32_t)(AT_Q + (wid * 16 + a_row) * AT_LD + k8 * 8 + a_koff) * 4);

    float m0 = -INFINITY, m1 = -INFINITY, l0 = 0.0f, l1 = 0.0f;
    float zacc[8][4];
#pragma unroll
    for (int jb = 0; jb < 8; jb++)
#pragma unroll
        for (int i = 0; i < 4; i++) zacc[jb][i] = 0.0f;

    uint32_t PwB = smb + (uint32_t)(AT_PW + wid * 16 * AT_LD) * 4;

    for (int kt = 0; kt < S_ / 64; kt++) {
        int buf = kt & 1;
        uint32_t ksb = smb + (uint32_t)(AT_K0 + buf * 4352) * 4;
        int vsf = AT_V0 + buf * 4352;

        CP_WAIT(0);
        __syncthreads();

        if (kt + 1 < S_ / 64) {
            const float* kb = kp + (size_t)(kt + 1) * 64 * D_;
            const float* vb = vp + (size_t)(kt + 1) * 64 * D_;
            uint32_t kd = smb + (uint32_t)(AT_K0 + (buf ^ 1) * 4352) * 4;
            uint32_t vd = smb + (uint32_t)(AT_V0 + (buf ^ 1) * 4352) * 4;
#pragma unroll
            for (int it = 0; it < 4; it++) {
                int i = tid + it * 256;
                int row = i >> 4, seg = i & 15;
                cpa16(kd + (uint32_t)(row * AT_LD + seg * 4) * 4, kb + row * 64 + seg * 4);
                cpa16(vd + (uint32_t)(row * AT_LD + seg * 4) * 4, vb + row * 64 + seg * 4);
            }
            CP_COMMIT();
        }

#pragma unroll
        for (int it = 0; it < 16; it++) {
            int i = tid + it * 256;
            int d = i >> 6, t = i & 63;
            sm[AT_VT + d * AT_LD + t] = sm[vsf + t * AT_LD + d];
        }
        __syncthreads();

        float sacc[8][4];
#pragma unroll
        for (int jb = 0; jb < 8; jb++)
#pragma unroll
            for (int i = 0; i < 4; i++) sacc[jb][i] = 0.0f;
#pragma unroll
        for (int k8 = 0; k8 < 8; k8++) {
            uint32_t bf[4][4];
#pragma unroll
            for (int nb = 0; nb < 4; nb++)
                ldmx4(bf[nb], ksb + (uint32_t)((nb * 16 + b_row) * AT_LD + k8 * 8 + b_koff) * 4);
#pragma unroll
            for (int nb = 0; nb < 4; nb++) {
                mma_tf32(sacc[nb * 2],     qf[k8], bf[nb]);
                mma_tf32(sacc[nb * 2 + 1], qf[k8], bf[nb] + 2);
            }
        }
#pragma unroll
        for (int jb = 0; jb < 8; jb++)
#pragma unroll
            for (int i = 0; i < 4; i++) sacc[jb][i] *= (1.0f / 64.0f);

        float t0 = -INFINITY, t1 = -INFINITY;
#pragma unroll
        for (int jb = 0; jb < 8; jb++) {
            t0 = fmaxf(t0, fmaxf(sacc[jb][0], sacc[jb][1]));
            t1 = fmaxf(t1, fmaxf(sacc[jb][2], sacc[jb][3]));
        }
#pragma unroll
        for (int o = 1; o <= 2; o <<= 1) {
            t0 = fmaxf(t0, __shfl_xor_sync(0xffffffffu, t0, o));
            t1 = fmaxf(t1, __shfl_xor_sync(0xffffffffu, t1, o));
        }
        float nm0 = fmaxf(m0, t0), nm1 = fmaxf(m1, t1);
        float c0 = __expf(m0 - nm0), c1 = __expf(m1 - nm1);
        l0 *= c0; l1 *= c1;
#pragma unroll
        for (int jb = 0; jb < 8; jb++) {
            zacc[jb][0] *= c0; zacc[jb][1] *= c0;
            zacc[jb][2] *= c1; zacc[jb][3] *= c1;
        }
        float ps0 = 0.0f, ps1 = 0.0f;
#pragma unroll
        for (int jb = 0; jb < 8; jb++) {
            float p;
            p = __expf(sacc[jb][0] - nm0); sacc[jb][0] = p; ps0 += p;
            p = __expf(sacc[jb][1] - nm0); sacc[jb][1] = p; ps0 += p;
            p = __expf(sacc[jb][2] - nm1); sacc[jb][2] = p; ps1 += p;
            p = __expf(sacc[jb][3] - nm1); sacc[jb][3] = p; ps1 += p;
        }
#pragma unroll
        for (int o = 1; o <= 2; o <<= 1) {
            ps0 += __shfl_xor_sync(0xffffffffu, ps0, o);
            ps1 += __shfl_xor_sync(0xffffffffu, ps1, o);
        }
        l0 += ps0; l1 += ps1; m0 = nm0; m1 = nm1;

        float* Pf = sm + AT_PW + wid * 16 * AT_LD;
#pragma unroll
        for (int jb = 0; jb < 8; jb++) {
            int col = jb * 8 + 2 * qid;
            float2 u0 = { sacc[jb][0], sacc[jb][1] };
            float2 u1 = { sacc[jb][2], sacc[jb][3] };
            *reinterpret_cast<float2*>(Pf + grp * AT_LD + col) = u0;
            *reinterpret_cast<float2*>(Pf + (grp + 8) * AT_LD + col) = u1;
        }
        __syncwarp();

#pragma unroll
        for (int t8 = 0; t8 < 8; t8++) {
            uint32_t pa[4];
            ldmx4(pa, PwB + (uint32_t)(a_row * AT_LD + t8 * 8 + a_koff) * 4);
            uint32_t vf[4][4];
#pragma unroll
            for (int nb = 0; nb < 4; nb++)
                ldmx4(vf[nb], smb + (uint32_t)(AT_VT + (nb * 16 + b_row) * AT_LD + t8 * 8 + b_koff) * 4);
#pragma unroll
            for (int nb = 0; nb < 4; nb++) {
                mma_tf32(zacc[nb * 2],     pa, vf[nb]);
                mma_tf32(zacc[nb * 2 + 1], pa, vf[nb] + 2);
            }
        }
    }

    // epilogue: z / l -> fp16 g_zh[b,s,h*64+d]
    float i0 = 1.0f / l0, i1 = 1.0f / l1;
    int s0 = qt * 128 + wid * 16 + grp;
    __half* z0 = g_zh + ((size_t)(b * S_ + s0)) * HD_ + h * D_;
    __half* z1 = z0 + (size_t)8 * HD_;
#pragma unroll
    for (int jb = 0; jb < 8; jb++) {
        int col = jb * 8 + 2 * qid;
        *reinterpret_cast<__half2*>(z0 + col) =
            __floats2half2_rn(zacc[jb][0] * i0, zacc[jb][1] * i0);
        *reinterpret_cast<__half2*>(z1 + col) =
            __floats2half2_rn(zacc[jb][2] * i1, zacc[jb][3] * i1);
    }
}

// ---------------------------------------------------------------------------
// K4: LM head via mma.sync fp16 m16n8k16: out = relu(Zh @ Wh^T + b)
// CTA 128x128, BK=64, 256 thr (warps 2M x 4N, warp tile 64x32),
// 2-stage cp.async. LD=72 halves (144B rows -> conflict-free ldmatrix).
// ---------------------------------------------------------------------------
#define LH_BK 64
#define LH_LD 72                          // halves per smem row
#define LH_TILE_H (128 * LH_LD)           // 9216 halves per matrix tile
#define LH_STAGE_B (2 * LH_TILE_H * 2)    // 36864 bytes per stage (A+B)
#define LH_SMEM_BYTES (2 * LH_STAGE_B)    // 73728

__device__ __forceinline__ void lh_load_stage(int ks, uint32_t base,
                                              int rb, int cb, int tid) {
    int k0 = ks * LH_BK;
    uint32_t aB = base, bB = base + LH_TILE_H * 2;
#pragma unroll
    for (int it = 0; it < 4; it++) {
        int i = tid + it * 256;
        int row = i >> 3, seg = i & 7;              // seg*8 halves = 16B
        cpa16(aB + (uint32_t)(row * LH_LD + seg * 8) * 2,
              g_zh + (size_t)(rb + row) * HD_ + k0 + seg * 8);
    }
#pragma unroll
    for (int it = 0; it < 4; it++) {
        int i = tid + it * 256;
        int row = i >> 3, seg = i & 7;
        cpa16(bB + (uint32_t)(row * LH_LD + seg * 8) * 2,
              g_wth + (size_t)(cb + row) * HD_ + k0 + seg * 8);
    }
}

__global__ void __launch_bounds__(256)
lm_head_f16_kernel(const float* __restrict__ bias, float* __restrict__ out) {
    extern __shared__ float sm[];
    uint32_t smb = smem_u32(sm);

    int tid = threadIdx.x, lane = tid & 31, wid = tid >> 5;
    int rb = blockIdx.x * 128;
    int cb = blockIdx.y * 128;
    int warp_m = wid & 1, warp_n = wid >> 1;

    int lmr = lane & 7, mat = lane >> 3;
    int a_row  = warp_m * 64 + (mat & 1) * 8 + lmr;
    int a_koff = (mat >> 1) * 8;                    // halves
    int b_row  = warp_n * 32 + (mat >> 1) * 8 + lmr;
    int b_koff = (mat & 1) * 8;

    float acc[4][4][4];
#pragma unroll
    for (int mt = 0; mt < 4; mt++)
#pragma unroll
        for (int nt = 0; nt < 4; nt++)
#pragma unroll
            for (int i = 0; i < 4; i++) acc[mt][nt][i] = 0.0f;

    lh_load_stage(0, smb, rb, cb, tid);
    CP_COMMIT();

    const int NS = HD_ / LH_BK;   // 16
    for (int ks = 0; ks < NS; ks++) {
        if (ks + 1 < NS) {
            lh_load_stage(ks + 1, smb + ((ks + 1) & 1) * LH_STAGE_B, rb, cb, tid);
            CP_COMMIT();
            CP_WAIT(1);
        } else {
            CP_WAIT(0);
        }
        __syncthreads();

        uint32_t Au = smb + (ks & 1) * LH_STAGE_B;
        uint32_t Bu = Au + LH_TILE_H * 2;
#pragma unroll
        for (int k16 = 0; k16 < 4; k16++) {
            int kh = k16 * 16;                      // halves
            uint32_t af[4][4], bf[2][4];
#pragma unroll
            for (int mt = 0; mt < 4; mt++)
                ldmx4(af[mt], Au + (uint32_t)((a_row + mt * 16) * LH_LD + kh + a_koff) * 2);
#pragma unroll
            for (int ng = 0; ng < 2; ng++)
                ldmx4(bf[ng], Bu + (uint32_t)((b_row + ng * 16) * LH_LD + kh + b_koff) * 2);
#pragma unroll
            for (int mt = 0; mt < 4; mt++)
#pragma unroll
                for (int nt = 0; nt < 4; nt++)
                    mma_f16(acc[mt][nt], af[mt], bf[nt >> 1] + (nt & 1) * 2);
        }
        __syncthreads();
    }

    int grp = lane >> 2, qid = lane & 3;
#pragma unroll
    for (int nt = 0; nt < 4; nt++) {
        int col = cb + warp_n * 32 + nt * 8 + qid * 2;
        const float2 bb = *reinterpret_cast<const float2*>(bias + col);
#pragma unroll
        for (int mt = 0; mt < 4; mt++) {
            int r0 = rb + warp_m * 64 + mt * 16 + grp;
            float2 v0, v1;
            v0.x = fmaxf(acc[mt][nt][0] + bb.x, 0.0f);
            v0.y = fmaxf(acc[mt][nt][1] + bb.y, 0.0f);
            v1.x = fmaxf(acc[mt][nt][2] + bb.x, 0.0f);
            v1.y = fmaxf(acc[mt][nt][3] + bb.y, 0.0f);
            *reinterpret_cast<float2*>(out + (size_t)r0 * V_ + col) = v0;
            *reinterpret_cast<float2*>(out + (size_t)(r0 + 8) * V_ + col) = v1;
        }
    }
}

// ---------------------------------------------------------------------------
extern "C" void kernel_launch(void* const* d_in, const int* in_sizes, int n_in,
                              void* d_out, int out_size) {
    const int*   x    = (const int*)d_in[0];
    const float* emb  = (const float*)d_in[1];
    const float* pos  = (const float*)d_in[2];
    const float* wq   = (const float*)d_in[3];
    const float* wk   = (const float*)d_in[4];
    const float* wv   = (const float*)d_in[5];
    const float* linw = (const float*)d_in[6];
    const float* linb = (const float*)d_in[7];
    float* out = (float*)d_out;

    static int smem_set = 0;
    if (!smem_set) {
        cudaFuncSetAttribute(lm_head_f16_kernel,
                             cudaFuncAttributeMaxDynamicSharedMemorySize, LH_SMEM_BYTES);
        cudaFuncSetAttribute(qkv_mma_kernel,
                             cudaFuncAttributeMaxDynamicSharedMemorySize, QP_SMEM_BYTES);
        cudaFuncSetAttribute(attn_mma_kernel,
                             cudaFuncAttributeMaxDynamicSharedMemorySize, AT_SMEM_BYTES);
        smem_set = 1;
    }

    wqkv_prep_kernel<<<dim3(48, E_ / 32, D_ / 32), dim3(32, 8)>>>(wq, wk, wv);
    wt_prep_kernel<<<dim3(V_ / 32, HD_ / 32), dim3(32, 8)>>>(linw);
    embed_gelu_kernel<<<BS_, 256>>>(x, emb, pos);
    qkv_mma_kernel<<<dim3(BS_ / 128, 48), 256, QP_SMEM_BYTES>>>();
    attn_mma_kernel<<<dim3(S_ / 128, H_, B_), 256, AT_SMEM_BYTES>>>();
    lm_head_f16_kernel<<<dim3(BS_ / 128, V_ / 128), 256, LH_SMEM_BYTES>>>(linb, out);
}

// round 9
// speedup vs baseline: 7.8446x; 1.2638x over previous
#include <cuda_runtime.h>
#include <cuda_fp16.h>
#include <math.h>
#include <stdint.h>

// ---------------------------------------------------------------------------
// AttentionLM: embed+pos -> gelu -> per-head QKV proj -> softmax attention
// (buggy /D scaling, no mask) -> concat heads -> lm head (relu(zW+b))
// Shapes: B=2 S=2048 E=1024 H=16 D=64 V=32000
// All GEMMs on mma.sync fp16 m16n8k16 (f32 accum).
// (plain sm_103 ptxas target rejects tcgen05 — learned R4)
// ---------------------------------------------------------------------------

#define B_  2
#define S_  2048
#define E_  1024
#define H_  16
#define D_  64
#define V_  32000
#define BS_ (B_ * S_)          // 4096
#define HD_ (H_ * D_)          // 1024

// scratch (no cudaMalloc allowed)
__device__ __half g_hh[BS_ * E_];              // gelu(embed+pos), fp16
__device__ __half g_qh[B_ * H_ * S_ * D_];
__device__ __half g_kh[B_ * H_ * S_ * D_];
__device__ __half g_vh[B_ * H_ * S_ * D_];
__device__ __half g_zh[BS_ * HD_];             // attention output, fp16
__device__ __half g_wth[(size_t)V_ * HD_];     // lm W transposed fp16: [V][K]
__device__ __half g_wqkvh[3 * H_ * D_ * E_];   // packed qkv W fp16: [3*H*D][E]

__device__ __forceinline__ float gelu_erf(float v) {
    return 0.5f * v * (1.0f + erff(v * 0.70710678118654752f));
}
__device__ __forceinline__ uint32_t smem_u32(const void* p) {
    uint32_t a;
    asm("{ .reg .u64 t; cvta.to.shared.u64 t, %1; cvt.u32.u64 %0, t; }"
        : "=r"(a) : "l"(p));
    return a;
}
__device__ __forceinline__ void cpa16(uint32_t dst, const void* src) {
    asm volatile("cp.async.cg.shared.global [%0], [%1], 16;"
                 :: "r"(dst), "l"(src) : "memory");
}
#define CP_COMMIT()  asm volatile("cp.async.commit_group;" ::: "memory")
#define CP_WAIT(n)   asm volatile("cp.async.wait_group %0;" :: "n"(n) : "memory")

__device__ __forceinline__ void ldmx4(uint32_t* r, uint32_t addr) {
    asm volatile("ldmatrix.sync.aligned.m8n8.x4.shared.b16 {%0,%1,%2,%3}, [%4];"
        : "=r"(r[0]), "=r"(r[1]), "=r"(r[2]), "=r"(r[3]) : "r"(addr));
}
__device__ __forceinline__ void ldmx4t(uint32_t* r, uint32_t addr) {
    asm volatile("ldmatrix.sync.aligned.m8n8.x4.trans.shared.b16 {%0,%1,%2,%3}, [%4];"
        : "=r"(r[0]), "=r"(r[1]), "=r"(r[2]), "=r"(r[3]) : "r"(addr));
}
__device__ __forceinline__ void mma_f16(float* d, const uint32_t* a, const uint32_t* b) {
    asm volatile("mma.sync.aligned.m16n8k16.row.col.f32.f16.f16.f32 "
        "{%0,%1,%2,%3}, {%4,%5,%6,%7}, {%8,%9}, {%0,%1,%2,%3};"
        : "+f"(d[0]), "+f"(d[1]), "+f"(d[2]), "+f"(d[3])
        : "r"(a[0]), "r"(a[1]), "r"(a[2]), "r"(a[3]), "r"(b[0]), "r"(b[1]));
}

// ---------------------------------------------------------------------------
// K1: h = gelu(embed[x] + pos) -> fp16
// ---------------------------------------------------------------------------
__global__ void embed_gelu_kernel(const int* __restrict__ x,
                                  const float* __restrict__ emb,
                                  const float* __restrict__ pos) {
    int t = blockIdx.x;
    int s = t & (S_ - 1);
    int row = x[t];
    const float4* e4 = reinterpret_cast<const float4*>(emb + (size_t)row * E_);
    const float4* p4 = reinterpret_cast<const float4*>(pos + (size_t)s * E_);
    int i = threadIdx.x;
    float4 a = e4[i], b = p4[i];
    __half2 lo = __floats2half2_rn(gelu_erf(a.x + b.x), gelu_erf(a.y + b.y));
    __half2 hi = __floats2half2_rn(gelu_erf(a.z + b.z), gelu_erf(a.w + b.w));
    __half2* h2 = reinterpret_cast<__half2*>(g_hh + (size_t)t * E_);
    h2[2 * i] = lo;
    h2[2 * i + 1] = hi;
}

// ---------------------------------------------------------------------------
// prep: pack qkv weights -> fp16 g_wqkvh[(proj*16+h)*64 + d][e]
// ---------------------------------------------------------------------------
__global__ void wqkv_prep_kernel(const float* __restrict__ wq,
                                 const float* __restrict__ wk,
                                 const float* __restrict__ wv) {
    __shared__ float t[32][33];
    int hp = blockIdx.x;
    int eb = blockIdx.y * 32, db = blockIdx.z * 32;
    int proj = hp >> 4, hh = hp & 15;
    const float* w = (proj == 0 ? wq : proj == 1 ? wk : wv) + (size_t)hh * E_ * D_;
    int tx = threadIdx.x, ty = threadIdx.y;
#pragma unroll
    for (int i = ty; i < 32; i += 8)
        t[i][tx] = w[(size_t)(eb + i) * D_ + db + tx];
    __syncthreads();
#pragma unroll
    for (int i = ty; i < 32; i += 8)
        g_wqkvh[(size_t)(hp * 64 + db + i) * E_ + eb + tx] = __float2half(t[tx][i]);
}

// ---------------------------------------------------------------------------
// prep: lm W transpose -> fp16: g_wth[v][k] = half(W[k][v])
// ---------------------------------------------------------------------------
__global__ void wt_prep_kernel(const float* __restrict__ W) {
    __shared__ float t[32][33];
    int vb = blockIdx.x * 32, kb = blockIdx.y * 32;
    int tx = threadIdx.x, ty = threadIdx.y;
#pragma unroll
    for (int i = ty; i < 32; i += 8)
        t[i][tx] = W[(size_t)(kb + i) * V_ + vb + tx];
    __syncthreads();
#pragma unroll
    for (int i = ty; i < 32; i += 8)
        g_wth[(size_t)(vb + i) * HD_ + kb + tx] = __float2half(t[tx][i]);
}

// ---------------------------------------------------------------------------
// K2: QKV via mma fp16.  CTA 128(M) x 64(N = one head-proj), BK=64 halves.
// grid (32, 48), 256 thr, warps 4M x 2N, warp tile 32x32.
// ---------------------------------------------------------------------------
#define QH_LD 72
#define QH_AH (128 * QH_LD)                  // 9216 halves
#define QH_BH (64 * QH_LD)                   // 4608
#define QH_STAGE_B ((QH_AH + QH_BH) * 2)     // 27648 bytes
#define QH_SMEM_BYTES (2 * QH_STAGE_B)       // 55296

__global__ void __launch_bounds__(256)
qkv_mma_kernel() {
    extern __shared__ __half smh[];
    uint32_t smb = smem_u32(smh);

    int tid = threadIdx.x, lane = tid & 31, wid = tid >> 5;
    int rb = blockIdx.x * 128;
    int hp = blockIdx.y;
    int warp_m = wid & 3, warp_n = wid >> 2;

    int lmr = lane & 7, mat = lane >> 3;
    int grp = lane >> 2, qid = lane & 3;
    int a_row  = warp_m * 32 + (mat & 1) * 8 + lmr;
    int a_koff = (mat >> 1) * 8;                 // halves
    int b_rloc = (mat >> 1) * 8 + lmr;
    int b_koff = (mat & 1) * 8;

    const __half* Bsrc = g_wqkvh + (size_t)hp * 64 * E_;

    float acc[2][4][4];
#pragma unroll
    for (int mt = 0; mt < 2; mt++)
#pragma unroll
        for (int nt = 0; nt < 4; nt++)
#pragma unroll
            for (int i = 0; i < 4; i++) acc[mt][nt][i] = 0.0f;

    auto load_stage = [&](int ks, uint32_t base) {
        int k0 = ks * 64;
        uint32_t aB = base, bB = base + QH_AH * 2;
#pragma unroll
        for (int it = 0; it < 4; it++) {             // A: 128 rows x 8 segs
            int i = tid + it * 256;
            int row = i >> 3, seg = i & 7;
            cpa16(aB + (uint32_t)(row * QH_LD + seg * 8) * 2,
                  g_hh + (size_t)(rb + row) * E_ + k0 + seg * 8);
        }
#pragma unroll
        for (int it = 0; it < 2; it++) {             // B: 64 rows x 8 segs
            int i = tid + it * 256;
            int row = i >> 3, seg = i & 7;
            cpa16(bB + (uint32_t)(row * QH_LD + seg * 8) * 2,
                  Bsrc + (size_t)row * E_ + k0 + seg * 8);
        }
    };

    load_stage(0, smb);
    CP_COMMIT();

    const int NS = E_ / 64;   // 16
    for (int ks = 0; ks < NS; ks++) {
        if (ks + 1 < NS) {
            load_stage(ks + 1, smb + ((ks + 1) & 1) * QH_STAGE_B);
            CP_COMMIT();
            CP_WAIT(1);
        } else {
            CP_WAIT(0);
        }
        __syncthreads();

        uint32_t Au = smb + (ks & 1) * QH_STAGE_B;
        uint32_t Bu = Au + QH_AH * 2;
#pragma unroll
        for (int k16 = 0; k16 < 4; k16++) {
            int kh = k16 * 16;
            uint32_t af[2][4], bf[2][4];
#pragma unroll
            for (int mt = 0; mt < 2; mt++)
                ldmx4(af[mt], Au + (uint32_t)((a_row + mt * 16) * QH_LD + kh + a_koff) * 2);
#pragma unroll
            for (int ng = 0; ng < 2; ng++)
                ldmx4(bf[ng], Bu + (uint32_t)((warp_n * 32 + ng * 16 + b_rloc) * QH_LD + kh + b_koff) * 2);
#pragma unroll
            for (int mt = 0; mt < 2; mt++)
#pragma unroll
                for (int nt = 0; nt < 4; nt++)
                    mma_f16(acc[mt][nt], af[mt], bf[nt >> 1] + (nt & 1) * 2);
        }
        __syncthreads();
    }

    int proj = hp >> 4, hh = hp & 15;
    __half* outb = (proj == 0 ? g_qh : proj == 1 ? g_kh : g_vh);
#pragma unroll
    for (int mt = 0; mt < 2; mt++) {
        int row = rb + warp_m * 32 + mt * 16 + grp;
        int bsel = row >> 11, s = row & (S_ - 1);
        __half* p0 = outb + ((size_t)(bsel * H_ + hh) * S_ + s) * D_;
        __half* p1 = p0 + 8 * D_;
#pragma unroll
        for (int nt = 0; nt < 4; nt++) {
            int col = warp_n * 32 + nt * 8 + 2 * qid;
            *reinterpret_cast<__half2*>(p0 + col) =
                __floats2half2_rn(acc[mt][nt][0], acc[mt][nt][1]);
            *reinterpret_cast<__half2*>(p1 + col) =
                __floats2half2_rn(acc[mt][nt][2], acc[mt][nt][3]);
        }
    }
}

// ---------------------------------------------------------------------------
// K3: flash attention on mma fp16. V consumed via ldmatrix.trans (no explicit
// transpose pass). 128 q-rows/CTA, 8 warps x 16 rows, 64-key tiles, double buf.
// scores/64 (faithful buggy double scale). grid (16, H, B), 256 thr.
// ---------------------------------------------------------------------------
#define AH_LD 72
#define AH_Q   0                         // 128*72 = 9216 halves
#define AH_K0  9216                      // 2 x 64*72 = 9216
#define AH_V0  18432                     // 2 x 4608
#define AH_PW  27648                     // 8 x 16*72 = 9216
#define AH_TOTH 36864
#define AH_SMEM_BYTES (AH_TOTH * 2)      // 73728
#define AH_BUFH 4608                     // halves per K/V buffer

__global__ void __launch_bounds__(256)
attn_mma_kernel() {
    extern __shared__ __half smh[];
    uint32_t smb = smem_u32(smh);

    int tid = threadIdx.x, lane = tid & 31, wid = tid >> 5;
    int qt = blockIdx.x, h = blockIdx.y, b = blockIdx.z;
    int bh = b * H_ + h;
    const __half* qp = g_qh + ((size_t)bh * S_ + qt * 128) * D_;
    const __half* kp = g_kh + (size_t)bh * S_ * D_;
    const __half* vp = g_vh + (size_t)bh * S_ * D_;

    int lmr = lane & 7, mat = lane >> 3;
    int grp = lane >> 2, qid = lane & 3;
    int a_row  = (mat & 1) * 8 + lmr;     // warp-local A rows (0..15)
    int a_koff = (mat >> 1) * 8;          // halves
    int b_rloc = (mat >> 1) * 8 + lmr;    // non-trans B row pattern
    int b_koff = (mat & 1) * 8;
    int vt_row = (mat & 1) * 8 + lmr;     // trans V: t-row pattern
    int vt_col = (mat >> 1) * 8;          // trans V: d-col offset (halves)

    // preload K/V tile 0
#pragma unroll
    for (int it = 0; it < 2; it++) {
        int i = tid + it * 256;
        int row = i >> 3, seg = i & 7;
        cpa16(smb + (uint32_t)(AH_K0 + row * AH_LD + seg * 8) * 2, kp + row * 64 + seg * 8);
        cpa16(smb + (uint32_t)(AH_V0 + row * AH_LD + seg * 8) * 2, vp + row * 64 + seg * 8);
    }
    CP_COMMIT();

    // load Q tile (128 rows x 64 halves)
#pragma unroll
    for (int it = 0; it < 4; it++) {
        int i = tid + it * 256;
        int row = i >> 3, seg = i & 7;
        *reinterpret_cast<float4*>(smh + AH_Q + row * AH_LD + seg * 8) =
            *reinterpret_cast<const float4*>(qp + (size_t)row * 64 + seg * 8);
    }
    __syncthreads();

    // Q fragments in registers (4 k16 steps)
    uint32_t qf[4][4];
#pragma unroll
    for (int k16 = 0; k16 < 4; k16++)
        ldmx4(qf[k16], smb + (uint32_t)(AH_Q + (wid * 16 + a_row) * AH_LD + k16 * 16 + a_koff) * 2);

    float m0 = -INFINITY, m1 = -INFINITY, l0 = 0.0f, l1 = 0.0f;
    float zacc[8][4];
#pragma unroll
    for (int jb = 0; jb < 8; jb++)
#pragma unroll
        for (int i = 0; i < 4; i++) zacc[jb][i] = 0.0f;

    uint32_t PwB = smb + (uint32_t)(AH_PW + wid * 16 * AH_LD) * 2;

    for (int kt = 0; kt < S_ / 64; kt++) {
        int buf = kt & 1;
        uint32_t ksb = smb + (uint32_t)(AH_K0 + buf * AH_BUFH) * 2;
        uint32_t vsb = smb + (uint32_t)(AH_V0 + buf * AH_BUFH) * 2;

        CP_WAIT(0);
        __syncthreads();

        if (kt + 1 < S_ / 64) {
            const __half* kb = kp + (size_t)(kt + 1) * 64 * D_;
            const __half* vb = vp + (size_t)(kt + 1) * 64 * D_;
            uint32_t kd = smb + (uint32_t)(AH_K0 + (buf ^ 1) * AH_BUFH) * 2;
            uint32_t vd = smb + (uint32_t)(AH_V0 + (buf ^ 1) * AH_BUFH) * 2;
#pragma unroll
            for (int it = 0; it < 2; it++) {
                int i = tid + it * 256;
                int row = i >> 3, seg = i & 7;
                cpa16(kd + (uint32_t)(row * AH_LD + seg * 8) * 2, kb + row * 64 + seg * 8);
                cpa16(vd + (uint32_t)(row * AH_LD + seg * 8) * 2, vb + row * 64 + seg * 8);
            }
            CP_COMMIT();
        }

        // S = Q K^T  (64 keys = 8 n8 groups)
        float sacc[8][4];
#pragma unroll
        for (int jb = 0; jb < 8; jb++)
#pragma unroll
            for (int i = 0; i < 4; i++) sacc[jb][i] = 0.0f;
#pragma unroll
        for (int k16 = 0; k16 < 4; k16++) {
            uint32_t bf[4][4];
#pragma unroll
            for (int nb = 0; nb < 4; nb++)
                ldmx4(bf[nb], ksb + (uint32_t)((nb * 16 + b_rloc) * AH_LD + k16 * 16 + b_koff) * 2);
#pragma unroll
            for (int nb = 0; nb < 4; nb++) {
                mma_f16(sacc[nb * 2],     qf[k16], bf[nb]);
                mma_f16(sacc[nb * 2 + 1], qf[k16], bf[nb] + 2);
            }
        }
#pragma unroll
        for (int jb = 0; jb < 8; jb++)
#pragma unroll
            for (int i = 0; i < 4; i++) sacc[jb][i] *= (1.0f / 64.0f);

        // online softmax (rows grp / grp+8; reduce over qid lanes)
        float t0 = -INFINITY, t1 = -INFINITY;
#pragma unroll
        for (int jb = 0; jb < 8; jb++) {
            t0 = fmaxf(t0, fmaxf(sacc[jb][0], sacc[jb][1]));
            t1 = fmaxf(t1, fmaxf(sacc[jb][2], sacc[jb][3]));
        }
#pragma unroll
        for (int o = 1; o <= 2; o <<= 1) {
            t0 = fmaxf(t0, __shfl_xor_sync(0xffffffffu, t0, o));
            t1 = fmaxf(t1, __shfl_xor_sync(0xffffffffu, t1, o));
        }
        float nm0 = fmaxf(m0, t0), nm1 = fmaxf(m1, t1);
        float c0 = __expf(m0 - nm0), c1 = __expf(m1 - nm1);
        l0 *= c0; l1 *= c1;
#pragma unroll
        for (int jb = 0; jb < 8; jb++) {
            zacc[jb][0] *= c0; zacc[jb][1] *= c0;
            zacc[jb][2] *= c1; zacc[jb][3] *= c1;
        }
        float ps0 = 0.0f, ps1 = 0.0f;
#pragma unroll
        for (int jb = 0; jb < 8; jb++) {
            float p;
            p = __expf(sacc[jb][0] - nm0); sacc[jb][0] = p; ps0 += p;
            p = __expf(sacc[jb][1] - nm0); sacc[jb][1] = p; ps0 += p;
            p = __expf(sacc[jb][2] - nm1); sacc[jb][2] = p; ps1 += p;
            p = __expf(sacc[jb][3] - nm1); sacc[jb][3] = p; ps1 += p;
        }
#pragma unroll
        for (int o = 1; o <= 2; o <<= 1) {
            ps0 += __shfl_xor_sync(0xffffffffu, ps0, o);
            ps1 += __shfl_xor_sync(0xffffffffu, ps1, o);
        }
        l0 += ps0; l1 += ps1; m0 = nm0; m1 = nm1;

        // stage P (fp16) in warp-private smem
        __half* Pf = smh + AH_PW + wid * 16 * AH_LD;
#pragma unroll
        for (int jb = 0; jb < 8; jb++) {
            int col = jb * 8 + 2 * qid;
            *reinterpret_cast<__half2*>(Pf + grp * AH_LD + col) =
                __floats2half2_rn(sacc[jb][0], sacc[jb][1]);
            *reinterpret_cast<__half2*>(Pf + (grp + 8) * AH_LD + col) =
                __floats2half2_rn(sacc[jb][2], sacc[jb][3]);
        }
        __syncwarp();

        // Z += P V  (V via ldmatrix.trans on [t][d] tile)
#pragma unroll
        for (int t16 = 0; t16 < 4; t16++) {
            uint32_t pa[4];
            ldmx4(pa, PwB + (uint32_t)(a_row * AH_LD + t16 * 16 + a_koff) * 2);
#pragma unroll
            for (int nb = 0; nb < 4; nb++) {
                uint32_t vf[4];
                ldmx4t(vf, vsb + (uint32_t)((t16 * 16 + vt_row) * AH_LD + nb * 16 + vt_col) * 2);
                mma_f16(zacc[nb * 2],     pa, vf);
                mma_f16(zacc[nb * 2 + 1], pa, vf + 2);
            }
        }
    }

    // epilogue: z / l -> fp16 g_zh[b,s,h*64+d]
    float i0 = 1.0f / l0, i1 = 1.0f / l1;
    int s0 = qt * 128 + wid * 16 + grp;
    __half* z0 = g_zh + ((size_t)(b * S_ + s0)) * HD_ + h * D_;
    __half* z1 = z0 + (size_t)8 * HD_;
#pragma unroll
    for (int jb = 0; jb < 8; jb++) {
        int col = jb * 8 + 2 * qid;
        *reinterpret_cast<__half2*>(z0 + col) =
            __floats2half2_rn(zacc[jb][0] * i0, zacc[jb][1] * i0);
        *reinterpret_cast<__half2*>(z1 + col) =
            __floats2half2_rn(zacc[jb][2] * i1, zacc[jb][3] * i1);
    }
}

// ---------------------------------------------------------------------------
// K4: LM head via mma.sync fp16 m16n8k16 (unchanged from R8)
// ---------------------------------------------------------------------------
#define LH_BK 64
#define LH_LD 72
#define LH_TILE_H (128 * LH_LD)
#define LH_STAGE_B (2 * LH_TILE_H * 2)
#define LH_SMEM_BYTES (2 * LH_STAGE_B)    // 73728

__device__ __forceinline__ void lh_load_stage(int ks, uint32_t base,
                                              int rb, int cb, int tid) {
    int k0 = ks * LH_BK;
    uint32_t aB = base, bB = base + LH_TILE_H * 2;
#pragma unroll
    for (int it = 0; it < 4; it++) {
        int i = tid + it * 256;
        int row = i >> 3, seg = i & 7;
        cpa16(aB + (uint32_t)(row * LH_LD + seg * 8) * 2,
              g_zh + (size_t)(rb + row) * HD_ + k0 + seg * 8);
    }
#pragma unroll
    for (int it = 0; it < 4; it++) {
        int i = tid + it * 256;
        int row = i >> 3, seg = i & 7;
        cpa16(bB + (uint32_t)(row * LH_LD + seg * 8) * 2,
              g_wth + (size_t)(cb + row) * HD_ + k0 + seg * 8);
    }
}

__global__ void __launch_bounds__(256)
lm_head_f16_kernel(const float* __restrict__ bias, float* __restrict__ out) {
    extern __shared__ float sm[];
    uint32_t smb = smem_u32(sm);

    int tid = threadIdx.x, lane = tid & 31, wid = tid >> 5;
    int rb = blockIdx.x * 128;
    int cb = blockIdx.y * 128;
    int warp_m = wid & 1, warp_n = wid >> 1;

    int lmr = lane & 7, mat = lane >> 3;
    int a_row  = warp_m * 64 + (mat & 1) * 8 + lmr;
    int a_koff = (mat >> 1) * 8;
    int b_row  = warp_n * 32 + (mat >> 1) * 8 + lmr;
    int b_koff = (mat & 1) * 8;

    float acc[4][4][4];
#pragma unroll
    for (int mt = 0; mt < 4; mt++)
#pragma unroll
        for (int nt = 0; nt < 4; nt++)
#pragma unroll
            for (int i = 0; i < 4; i++) acc[mt][nt][i] = 0.0f;

    lh_load_stage(0, smb, rb, cb, tid);
    CP_COMMIT();

    const int NS = HD_ / LH_BK;
    for (int ks = 0; ks < NS; ks++) {
        if (ks + 1 < NS) {
            lh_load_stage(ks + 1, smb + ((ks + 1) & 1) * LH_STAGE_B, rb, cb, tid);
            CP_COMMIT();
            CP_WAIT(1);
        } else {
            CP_WAIT(0);
        }
        __syncthreads();

        uint32_t Au = smb + (ks & 1) * LH_STAGE_B;
        uint32_t Bu = Au + LH_TILE_H * 2;
#pragma unroll
        for (int k16 = 0; k16 < 4; k16++) {
            int kh = k16 * 16;
            uint32_t af[4][4], bf[2][4];
#pragma unroll
            for (int mt = 0; mt < 4; mt++)
                ldmx4(af[mt], Au + (uint32_t)((a_row + mt * 16) * LH_LD + kh + a_koff) * 2);
#pragma unroll
            for (int ng = 0; ng < 2; ng++)
                ldmx4(bf[ng], Bu + (uint32_t)((b_row + ng * 16) * LH_LD + kh + b_koff) * 2);
#pragma unroll
            for (int mt = 0; mt < 4; mt++)
#pragma unroll
                for (int nt = 0; nt < 4; nt++)
                    mma_f16(acc[mt][nt], af[mt], bf[nt >> 1] + (nt & 1) * 2);
        }
        __syncthreads();
    }

    int grp = lane >> 2, qid = lane & 3;
#pragma unroll
    for (int nt = 0; nt < 4; nt++) {
        int col = cb + warp_n * 32 + nt * 8 + qid * 2;
        const float2 bb = *reinterpret_cast<const float2*>(bias + col);
#pragma unroll
        for (int mt = 0; mt < 4; mt++) {
            int r0 = rb + warp_m * 64 + mt * 16 + grp;
            float2 v0, v1;
            v0.x = fmaxf(acc[mt][nt][0] + bb.x, 0.0f);
            v0.y = fmaxf(acc[mt][nt][1] + bb.y, 0.0f);
            v1.x = fmaxf(acc[mt][nt][2] + bb.x, 0.0f);
            v1.y = fmaxf(acc[mt][nt][3] + bb.y, 0.0f);
            *reinterpret_cast<float2*>(out + (size_t)r0 * V_ + col) = v0;
            *reinterpret_cast<float2*>(out + (size_t)(r0 + 8) * V_ + col) = v1;
        }
    }
}

// ---------------------------------------------------------------------------
extern "C" void kernel_launch(void* const* d_in, const int* in_sizes, int n_in,
                              void* d_out, int out_size) {
    const int*   x    = (const int*)d_in[0];
    const float* emb  = (const float*)d_in[1];
    const float* pos  = (const float*)d_in[2];
    const float* wq   = (const float*)d_in[3];
    const float* wk   = (const float*)d_in[4];
    const float* wv   = (const float*)d_in[5];
    const float* linw = (const float*)d_in[6];
    const float* linb = (const float*)d_in[7];
    float* out = (float*)d_out;

    static int smem_set = 0;
    if (!smem_set) {
        cudaFuncSetAttribute(lm_head_f16_kernel,
                             cudaFuncAttributeMaxDynamicSharedMemorySize, LH_SMEM_BYTES);
        cudaFuncSetAttribute(qkv_mma_kernel,
                             cudaFuncAttributeMaxDynamicSharedMemorySize, QH_SMEM_BYTES);
        cudaFuncSetAttribute(attn_mma_kernel,
                             cudaFuncAttributeMaxDynamicSharedMemorySize, AH_SMEM_BYTES);
        smem_set = 1;
    }

    wqkv_prep_kernel<<<dim3(48, E_ / 32, D_ / 32), dim3(32, 8)>>>(wq, wk, wv);
    wt_prep_kernel<<<dim3(V_ / 32, HD_ / 32), dim3(32, 8)>>>(linw);
    embed_gelu_kernel<<<BS_, 256>>>(x, emb, pos);
    qkv_mma_kernel<<<dim3(BS_ / 128, 48), 256, QH_SMEM_BYTES>>>();
    attn_mma_kernel<<<dim3(S_ / 128, H_, B_), 256, AH_SMEM_BYTES>>>();
    lm_head_f16_kernel<<<dim3(BS_ / 128, V_ / 128), 256, LH_SMEM_BYTES>>>(linb, out);
}

// round 10
// speedup vs baseline: 8.5307x; 1.0875x over previous
#include <cuda_runtime.h>
#include <cuda_fp16.h>
#include <math.h>
#include <stdint.h>

// ---------------------------------------------------------------------------
// AttentionLM: embed+pos -> gelu -> per-head QKV proj -> softmax attention
// (buggy /D scaling, no mask) -> concat heads -> lm head (relu(zW+b))
// Shapes: B=2 S=2048 E=1024 H=16 D=64 V=32000
// All GEMMs on mma.sync fp16 m16n8k16 (f32 accum); GEMM mainloops use a
// 3-stage cp.async ring with one __syncthreads per K-stage.
// (plain sm_103 ptxas target rejects tcgen05 — learned R4)
// ---------------------------------------------------------------------------

#define B_  2
#define S_  2048
#define E_  1024
#define H_  16
#define D_  64
#define V_  32000
#define BS_ (B_ * S_)          // 4096
#define HD_ (H_ * D_)          // 1024

// scratch (no cudaMalloc allowed)
__device__ __half g_hh[BS_ * E_];              // gelu(embed+pos), fp16
__device__ __half g_qh[B_ * H_ * S_ * D_];
__device__ __half g_kh[B_ * H_ * S_ * D_];
__device__ __half g_vh[B_ * H_ * S_ * D_];
__device__ __half g_zh[BS_ * HD_];             // attention output, fp16
__device__ __half g_wth[(size_t)V_ * HD_];     // lm W transposed fp16: [V][K]
__device__ __half g_wqkvh[3 * H_ * D_ * E_];   // packed qkv W fp16: [3*H*D][E]

__device__ __forceinline__ float gelu_erf(float v) {
    return 0.5f * v * (1.0f + erff(v * 0.70710678118654752f));
}
__device__ __forceinline__ uint32_t smem_u32(const void* p) {
    uint32_t a;
    asm("{ .reg .u64 t; cvta.to.shared.u64 t, %1; cvt.u32.u64 %0, t; }"
        : "=r"(a) : "l"(p));
    return a;
}
__device__ __forceinline__ void cpa16(uint32_t dst, const void* src) {
    asm volatile("cp.async.cg.shared.global [%0], [%1], 16;"
                 :: "r"(dst), "l"(src) : "memory");
}
#define CP_COMMIT()  asm volatile("cp.async.commit_group;" ::: "memory")
#define CP_WAIT(n)   asm volatile("cp.async.wait_group %0;" :: "n"(n) : "memory")

__device__ __forceinline__ void ldmx4(uint32_t* r, uint32_t addr) {
    asm volatile("ldmatrix.sync.aligned.m8n8.x4.shared.b16 {%0,%1,%2,%3}, [%4];"
        : "=r"(r[0]), "=r"(r[1]), "=r"(r[2]), "=r"(r[3]) : "r"(addr));
}
__device__ __forceinline__ void ldmx4t(uint32_t* r, uint32_t addr) {
    asm volatile("ldmatrix.sync.aligned.m8n8.x4.trans.shared.b16 {%0,%1,%2,%3}, [%4];"
        : "=r"(r[0]), "=r"(r[1]), "=r"(r[2]), "=r"(r[3]) : "r"(addr));
}
__device__ __forceinline__ void mma_f16(float* d, const uint32_t* a, const uint32_t* b) {
    asm volatile("mma.sync.aligned.m16n8k16.row.col.f32.f16.f16.f32 "
        "{%0,%1,%2,%3}, {%4,%5,%6,%7}, {%8,%9}, {%0,%1,%2,%3};"
        : "+f"(d[0]), "+f"(d[1]), "+f"(d[2]), "+f"(d[3])
        : "r"(a[0]), "r"(a[1]), "r"(a[2]), "r"(a[3]), "r"(b[0]), "r"(b[1]));
}

// ---------------------------------------------------------------------------
// K1: h = gelu(embed[x] + pos) -> fp16
// ---------------------------------------------------------------------------
__global__ void embed_gelu_kernel(const int* __restrict__ x,
                                  const float* __restrict__ emb,
                                  const float* __restrict__ pos) {
    int t = blockIdx.x;
    int s = t & (S_ - 1);
    int row = x[t];
    const float4* e4 = reinterpret_cast<const float4*>(emb + (size_t)row * E_);
    const float4* p4 = reinterpret_cast<const float4*>(pos + (size_t)s * E_);
    int i = threadIdx.x;
    float4 a = e4[i], b = p4[i];
    __half2 lo = __floats2half2_rn(gelu_erf(a.x + b.x), gelu_erf(a.y + b.y));
    __half2 hi = __floats2half2_rn(gelu_erf(a.z + b.z), gelu_erf(a.w + b.w));
    __half2* h2 = reinterpret_cast<__half2*>(g_hh + (size_t)t * E_);
    h2[2 * i] = lo;
    h2[2 * i + 1] = hi;
}

// ---------------------------------------------------------------------------
// prep: pack qkv weights -> fp16 g_wqkvh[(proj*16+h)*64 + d][e]
// ---------------------------------------------------------------------------
__global__ void wqkv_prep_kernel(const float* __restrict__ wq,
                                 const float* __restrict__ wk,
                                 const float* __restrict__ wv) {
    __shared__ float t[32][33];
    int hp = blockIdx.x;
    int eb = blockIdx.y * 32, db = blockIdx.z * 32;
    int proj = hp >> 4, hh = hp & 15;
    const float* w = (proj == 0 ? wq : proj == 1 ? wk : wv) + (size_t)hh * E_ * D_;
    int tx = threadIdx.x, ty = threadIdx.y;
#pragma unroll
    for (int i = ty; i < 32; i += 8)
        t[i][tx] = w[(size_t)(eb + i) * D_ + db + tx];
    __syncthreads();
#pragma unroll
    for (int i = ty; i < 32; i += 8)
        g_wqkvh[(size_t)(hp * 64 + db + i) * E_ + eb + tx] = __float2half(t[tx][i]);
}

// ---------------------------------------------------------------------------
// prep: lm W transpose -> fp16: g_wth[v][k] = half(W[k][v])
// ---------------------------------------------------------------------------
__global__ void wt_prep_kernel(const float* __restrict__ W) {
    __shared__ float t[32][33];
    int vb = blockIdx.x * 32, kb = blockIdx.y * 32;
    int tx = threadIdx.x, ty = threadIdx.y;
#pragma unroll
    for (int i = ty; i < 32; i += 8)
        t[i][tx] = W[(size_t)(kb + i) * V_ + vb + tx];
    __syncthreads();
#pragma unroll
    for (int i = ty; i < 32; i += 8)
        g_wth[(size_t)(vb + i) * HD_ + kb + tx] = __float2half(t[tx][i]);
}

// ---------------------------------------------------------------------------
// K2: QKV via mma fp16.  CTA 128(M) x 64(N = one head-proj), BK=64 halves.
// 3-stage cp.async ring, one __syncthreads per stage.
// grid (32, 48), 256 thr, warps 4M x 2N, warp tile 32x32.
// ---------------------------------------------------------------------------
#define QH_LD 72
#define QH_AH (128 * QH_LD)                  // 9216 halves
#define QH_BH (64 * QH_LD)                   // 4608
#define QH_STAGE_B ((QH_AH + QH_BH) * 2)     // 27648 bytes
#define QH_SMEM_BYTES (3 * QH_STAGE_B)       // 82944

__global__ void __launch_bounds__(256)
qkv_mma_kernel() {
    extern __shared__ __half smh[];
    uint32_t smb = smem_u32(smh);

    int tid = threadIdx.x, lane = tid & 31, wid = tid >> 5;
    int rb = blockIdx.x * 128;
    int hp = blockIdx.y;
    int warp_m = wid & 3, warp_n = wid >> 2;

    int lmr = lane & 7, mat = lane >> 3;
    int grp = lane >> 2, qid = lane & 3;
    int a_row  = warp_m * 32 + (mat & 1) * 8 + lmr;
    int a_koff = (mat >> 1) * 8;                 // halves
    int b_rloc = (mat >> 1) * 8 + lmr;
    int b_koff = (mat & 1) * 8;

    const __half* Bsrc = g_wqkvh + (size_t)hp * 64 * E_;

    float acc[2][4][4];
#pragma unroll
    for (int mt = 0; mt < 2; mt++)
#pragma unroll
        for (int nt = 0; nt < 4; nt++)
#pragma unroll
            for (int i = 0; i < 4; i++) acc[mt][nt][i] = 0.0f;

    auto load_stage = [&](int ks, uint32_t base) {
        int k0 = ks * 64;
        uint32_t aB = base, bB = base + QH_AH * 2;
#pragma unroll
        for (int it = 0; it < 4; it++) {             // A: 128 rows x 8 segs
            int i = tid + it * 256;
            int row = i >> 3, seg = i & 7;
            cpa16(aB + (uint32_t)(row * QH_LD + seg * 8) * 2,
                  g_hh + (size_t)(rb + row) * E_ + k0 + seg * 8);
        }
#pragma unroll
        for (int it = 0; it < 2; it++) {             // B: 64 rows x 8 segs
            int i = tid + it * 256;
            int row = i >> 3, seg = i & 7;
            cpa16(bB + (uint32_t)(row * QH_LD + seg * 8) * 2,
                  Bsrc + (size_t)row * E_ + k0 + seg * 8);
        }
    };

    load_stage(0, smb);
    CP_COMMIT();
    load_stage(1, smb + QH_STAGE_B);
    CP_COMMIT();

    const int NS = E_ / 64;   // 16
    int cur = 0;
    for (int ks = 0; ks < NS; ks++) {
        if (ks < NS - 1) { CP_WAIT(1); } else { CP_WAIT(0); }
        __syncthreads();

        uint32_t Au = smb + (uint32_t)cur * QH_STAGE_B;
        uint32_t Bu = Au + QH_AH * 2;
#pragma unroll
        for (int k16 = 0; k16 < 4; k16++) {
            int kh = k16 * 16;
            uint32_t af[2][4], bf[2][4];
#pragma unroll
            for (int mt = 0; mt < 2; mt++)
                ldmx4(af[mt], Au + (uint32_t)((a_row + mt * 16) * QH_LD + kh + a_koff) * 2);
#pragma unroll
            for (int ng = 0; ng < 2; ng++)
                ldmx4(bf[ng], Bu + (uint32_t)((warp_n * 32 + ng * 16 + b_rloc) * QH_LD + kh + b_koff) * 2);
#pragma unroll
            for (int mt = 0; mt < 2; mt++)
#pragma unroll
                for (int nt = 0; nt < 4; nt++)
                    mma_f16(acc[mt][nt], af[mt], bf[nt >> 1] + (nt & 1) * 2);
        }

        if (ks + 2 < NS) {
            int nxt = (cur == 0) ? 2 : cur - 1;      // (ks+2) % 3
            load_stage(ks + 2, smb + (uint32_t)nxt * QH_STAGE_B);
            CP_COMMIT();
        }
        cur = (cur == 2) ? 0 : cur + 1;
    }

    int proj = hp >> 4, hh = hp & 15;
    __half* outb = (proj == 0 ? g_qh : proj == 1 ? g_kh : g_vh);
#pragma unroll
    for (int mt = 0; mt < 2; mt++) {
        int row = rb + warp_m * 32 + mt * 16 + grp;
        int bsel = row >> 11, s = row & (S_ - 1);
        __half* p0 = outb + ((size_t)(bsel * H_ + hh) * S_ + s) * D_;
        __half* p1 = p0 + 8 * D_;
#pragma unroll
        for (int nt = 0; nt < 4; nt++) {
            int col = warp_n * 32 + nt * 8 + 2 * qid;
            *reinterpret_cast<__half2*>(p0 + col) =
                __floats2half2_rn(acc[mt][nt][0], acc[mt][nt][1]);
            *reinterpret_cast<__half2*>(p1 + col) =
                __floats2half2_rn(acc[mt][nt][2], acc[mt][nt][3]);
        }
    }
}

// ---------------------------------------------------------------------------
// K3: flash attention on mma fp16 (unchanged from R9).
// ---------------------------------------------------------------------------
#define AH_LD 72
#define AH_Q   0
#define AH_K0  9216
#define AH_V0  18432
#define AH_PW  27648
#define AH_TOTH 36864
#define AH_SMEM_BYTES (AH_TOTH * 2)      // 73728
#define AH_BUFH 4608

__global__ void __launch_bounds__(256)
attn_mma_kernel() {
    extern __shared__ __half smh[];
    uint32_t smb = smem_u32(smh);

    int tid = threadIdx.x, lane = tid & 31, wid = tid >> 5;
    int qt = blockIdx.x, h = blockIdx.y, b = blockIdx.z;
    int bh = b * H_ + h;
    const __half* qp = g_qh + ((size_t)bh * S_ + qt * 128) * D_;
    const __half* kp = g_kh + (size_t)bh * S_ * D_;
    const __half* vp = g_vh + (size_t)bh * S_ * D_;

    int lmr = lane & 7, mat = lane >> 3;
    int grp = lane >> 2, qid = lane & 3;
    int a_row  = (mat & 1) * 8 + lmr;
    int a_koff = (mat >> 1) * 8;
    int b_rloc = (mat >> 1) * 8 + lmr;
    int b_koff = (mat & 1) * 8;
    int vt_row = (mat & 1) * 8 + lmr;
    int vt_col = (mat >> 1) * 8;

#pragma unroll
    for (int it = 0; it < 2; it++) {
        int i = tid + it * 256;
        int row = i >> 3, seg = i & 7;
        cpa16(smb + (uint32_t)(AH_K0 + row * AH_LD + seg * 8) * 2, kp + row * 64 + seg * 8);
        cpa16(smb + (uint32_t)(AH_V0 + row * AH_LD + seg * 8) * 2, vp + row * 64 + seg * 8);
    }
    CP_COMMIT();

#pragma unroll
    for (int it = 0; it < 4; it++) {
        int i = tid + it * 256;
        int row = i >> 3, seg = i & 7;
        *reinterpret_cast<float4*>(smh + AH_Q + row * AH_LD + seg * 8) =
            *reinterpret_cast<const float4*>(qp + (size_t)row * 64 + seg * 8);
    }
    __syncthreads();

    uint32_t qf[4][4];
#pragma unroll
    for (int k16 = 0; k16 < 4; k16++)
        ldmx4(qf[k16], smb + (uint32_t)(AH_Q + (wid * 16 + a_row) * AH_LD + k16 * 16 + a_koff) * 2);

    float m0 = -INFINITY, m1 = -INFINITY, l0 = 0.0f, l1 = 0.0f;
    float zacc[8][4];
#pragma unroll
    for (int jb = 0; jb < 8; jb++)
#pragma unroll
        for (int i = 0; i < 4; i++) zacc[jb][i] = 0.0f;

    uint32_t PwB = smb + (uint32_t)(AH_PW + wid * 16 * AH_LD) * 2;

    for (int kt = 0; kt < S_ / 64; kt++) {
        int buf = kt & 1;
        uint32_t ksb = smb + (uint32_t)(AH_K0 + buf * AH_BUFH) * 2;
        uint32_t vsb = smb + (uint32_t)(AH_V0 + buf * AH_BUFH) * 2;

        CP_WAIT(0);
        __syncthreads();

        if (kt + 1 < S_ / 64) {
            const __half* kb = kp + (size_t)(kt + 1) * 64 * D_;
            const __half* vb = vp + (size_t)(kt + 1) * 64 * D_;
            uint32_t kd = smb + (uint32_t)(AH_K0 + (buf ^ 1) * AH_BUFH) * 2;
            uint32_t vd = smb + (uint32_t)(AH_V0 + (buf ^ 1) * AH_BUFH) * 2;
#pragma unroll
            for (int it = 0; it < 2; it++) {
                int i = tid + it * 256;
                int row = i >> 3, seg = i & 7;
                cpa16(kd + (uint32_t)(row * AH_LD + seg * 8) * 2, kb + row * 64 + seg * 8);
                cpa16(vd + (uint32_t)(row * AH_LD + seg * 8) * 2, vb + row * 64 + seg * 8);
            }
            CP_COMMIT();
        }

        float sacc[8][4];
#pragma unroll
        for (int jb = 0; jb < 8; jb++)
#pragma unroll
            for (int i = 0; i < 4; i++) sacc[jb][i] = 0.0f;
#pragma unroll
        for (int k16 = 0; k16 < 4; k16++) {
            uint32_t bf[4][4];
#pragma unroll
            for (int nb = 0; nb < 4; nb++)
                ldmx4(bf[nb], ksb + (uint32_t)((nb * 16 + b_rloc) * AH_LD + k16 * 16 + b_koff) * 2);
#pragma unroll
            for (int nb = 0; nb < 4; nb++) {
                mma_f16(sacc[nb * 2],     qf[k16], bf[nb]);
                mma_f16(sacc[nb * 2 + 1], qf[k16], bf[nb] + 2);
            }
        }
#pragma unroll
        for (int jb = 0; jb < 8; jb++)
#pragma unroll
            for (int i = 0; i < 4; i++) sacc[jb][i] *= (1.0f / 64.0f);

        float t0 = -INFINITY, t1 = -INFINITY;
#pragma unroll
        for (int jb = 0; jb < 8; jb++) {
            t0 = fmaxf(t0, fmaxf(sacc[jb][0], sacc[jb][1]));
            t1 = fmaxf(t1, fmaxf(sacc[jb][2], sacc[jb][3]));
        }
#pragma unroll
        for (int o = 1; o <= 2; o <<= 1) {
            t0 = fmaxf(t0, __shfl_xor_sync(0xffffffffu, t0, o));
            t1 = fmaxf(t1, __shfl_xor_sync(0xffffffffu, t1, o));
        }
        float nm0 = fmaxf(m0, t0), nm1 = fmaxf(m1, t1);
        float c0 = __expf(m0 - nm0), c1 = __expf(m1 - nm1);
        l0 *= c0; l1 *= c1;
#pragma unroll
        for (int jb = 0; jb < 8; jb++) {
            zacc[jb][0] *= c0; zacc[jb][1] *= c0;
            zacc[jb][2] *= c1; zacc[jb][3] *= c1;
        }
        float ps0 = 0.0f, ps1 = 0.0f;
#pragma unroll
        for (int jb = 0; jb < 8; jb++) {
            float p;
            p = __expf(sacc[jb][0] - nm0); sacc[jb][0] = p; ps0 += p;
            p = __expf(sacc[jb][1] - nm0); sacc[jb][1] = p; ps0 += p;
            p = __expf(sacc[jb][2] - nm1); sacc[jb][2] = p; ps1 += p;
            p = __expf(sacc[jb][3] - nm1); sacc[jb][3] = p; ps1 += p;
        }
#pragma unroll
        for (int o = 1; o <= 2; o <<= 1) {
            ps0 += __shfl_xor_sync(0xffffffffu, ps0, o);
            ps1 += __shfl_xor_sync(0xffffffffu, ps1, o);
        }
        l0 += ps0; l1 += ps1; m0 = nm0; m1 = nm1;

        __half* Pf = smh + AH_PW + wid * 16 * AH_LD;
#pragma unroll
        for (int jb = 0; jb < 8; jb++) {
            int col = jb * 8 + 2 * qid;
            *reinterpret_cast<__half2*>(Pf + grp * AH_LD + col) =
                __floats2half2_rn(sacc[jb][0], sacc[jb][1]);
            *reinterpret_cast<__half2*>(Pf + (grp + 8) * AH_LD + col) =
                __floats2half2_rn(sacc[jb][2], sacc[jb][3]);
        }
        __syncwarp();

#pragma unroll
        for (int t16 = 0; t16 < 4; t16++) {
            uint32_t pa[4];
            ldmx4(pa, PwB + (uint32_t)(a_row * AH_LD + t16 * 16 + a_koff) * 2);
#pragma unroll
            for (int nb = 0; nb < 4; nb++) {
                uint32_t vf[4];
                ldmx4t(vf, vsb + (uint32_t)((t16 * 16 + vt_row) * AH_LD + nb * 16 + vt_col) * 2);
                mma_f16(zacc[nb * 2],     pa, vf);
                mma_f16(zacc[nb * 2 + 1], pa, vf + 2);
            }
        }
    }

    float i0 = 1.0f / l0, i1 = 1.0f / l1;
    int s0 = qt * 128 + wid * 16 + grp;
    __half* z0 = g_zh + ((size_t)(b * S_ + s0)) * HD_ + h * D_;
    __half* z1 = z0 + (size_t)8 * HD_;
#pragma unroll
    for (int jb = 0; jb < 8; jb++) {
        int col = jb * 8 + 2 * qid;
        *reinterpret_cast<__half2*>(z0 + col) =
            __floats2half2_rn(zacc[jb][0] * i0, zacc[jb][1] * i0);
        *reinterpret_cast<__half2*>(z1 + col) =
            __floats2half2_rn(zacc[jb][2] * i1, zacc[jb][3] * i1);
    }
}

// ---------------------------------------------------------------------------
// K4: LM head via mma.sync fp16 m16n8k16. 3-stage cp.async ring, one
// __syncthreads per K-stage. CTA 128x128, BK=64, warps 2M x 4N (64x32 each).
// ---------------------------------------------------------------------------
#define LH_BK 64
#define LH_LD 72
#define LH_TILE_H (128 * LH_LD)
#define LH_STAGE_B (2 * LH_TILE_H * 2)     // 36864
#define LH_SMEM_BYTES (3 * LH_STAGE_B)     // 110592

__device__ __forceinline__ void lh_load_stage(int ks, uint32_t base,
                                              int rb, int cb, int tid) {
    int k0 = ks * LH_BK;
    uint32_t aB = base, bB = base + LH_TILE_H * 2;
#pragma unroll
    for (int it = 0; it < 4; it++) {
        int i = tid + it * 256;
        int row = i >> 3, seg = i & 7;
        cpa16(aB + (uint32_t)(row * LH_LD + seg * 8) * 2,
              g_zh + (size_t)(rb + row) * HD_ + k0 + seg * 8);
    }
#pragma unroll
    for (int it = 0; it < 4; it++) {
        int i = tid + it * 256;
        int row = i >> 3, seg = i & 7;
        cpa16(bB + (uint32_t)(row * LH_LD + seg * 8) * 2,
              g_wth + (size_t)(cb + row) * HD_ + k0 + seg * 8);
    }
}

__global__ void __launch_bounds__(256)
lm_head_f16_kernel(const float* __restrict__ bias, float* __restrict__ out) {
    extern __shared__ float sm[];
    uint32_t smb = smem_u32(sm);

    int tid = threadIdx.x, lane = tid & 31, wid = tid >> 5;
    int rb = blockIdx.x * 128;
    int cb = blockIdx.y * 128;
    int warp_m = wid & 1, warp_n = wid >> 1;

    int lmr = lane & 7, mat = lane >> 3;
    int a_row  = warp_m * 64 + (mat & 1) * 8 + lmr;
    int a_koff = (mat >> 1) * 8;
    int b_row  = warp_n * 32 + (mat >> 1) * 8 + lmr;
    int b_koff = (mat & 1) * 8;

    float acc[4][4][4];
#pragma unroll
    for (int mt = 0; mt < 4; mt++)
#pragma unroll
        for (int nt = 0; nt < 4; nt++)
#pragma unroll
            for (int i = 0; i < 4; i++) acc[mt][nt][i] = 0.0f;

    lh_load_stage(0, smb, rb, cb, tid);
    CP_COMMIT();
    lh_load_stage(1, smb + LH_STAGE_B, rb, cb, tid);
    CP_COMMIT();

    const int NS = HD_ / LH_BK;   // 16
    int cur = 0;
    for (int ks = 0; ks < NS; ks++) {
        if (ks < NS - 1) { CP_WAIT(1); } else { CP_WAIT(0); }
        __syncthreads();

        uint32_t Au = smb + (uint32_t)cur * LH_STAGE_B;
        uint32_t Bu = Au + LH_TILE_H * 2;
#pragma unroll
        for (int k16 = 0; k16 < 4; k16++) {
            int kh = k16 * 16;
            uint32_t af[4][4], bf[2][4];
#pragma unroll
            for (int mt = 0; mt < 4; mt++)
                ldmx4(af[mt], Au + (uint32_t)((a_row + mt * 16) * LH_LD + kh + a_koff) * 2);
#pragma unroll
            for (int ng = 0; ng < 2; ng++)
                ldmx4(bf[ng], Bu + (uint32_t)((b_row + ng * 16) * LH_LD + kh + b_koff) * 2);
#pragma unroll
            for (int mt = 0; mt < 4; mt++)
#pragma unroll
                for (int nt = 0; nt < 4; nt++)
                    mma_f16(acc[mt][nt], af[mt], bf[nt >> 1] + (nt & 1) * 2);
        }

        if (ks + 2 < NS) {
            int nxt = (cur == 0) ? 2 : cur - 1;      // (ks+2) % 3
            lh_load_stage(ks + 2, smb + (uint32_t)nxt * LH_STAGE_B, rb, cb, tid);
            CP_COMMIT();
        }
        cur = (cur == 2) ? 0 : cur + 1;
    }

    int grp = lane >> 2, qid = lane & 3;
#pragma unroll
    for (int nt = 0; nt < 4; nt++) {
        int col = cb + warp_n * 32 + nt * 8 + qid * 2;
        const float2 bb = *reinterpret_cast<const float2*>(bias + col);
#pragma unroll
        for (int mt = 0; mt < 4; mt++) {
            int r0 = rb + warp_m * 64 + mt * 16 + grp;
            float2 v0, v1;
            v0.x = fmaxf(acc[mt][nt][0] + bb.x, 0.0f);
            v0.y = fmaxf(acc[mt][nt][1] + bb.y, 0.0f);
            v1.x = fmaxf(acc[mt][nt][2] + bb.x, 0.0f);
            v1.y = fmaxf(acc[mt][nt][3] + bb.y, 0.0f);
            *reinterpret_cast<float2*>(out + (size_t)r0 * V_ + col) = v0;
            *reinterpret_cast<float2*>(out + (size_t)(r0 + 8) * V_ + col) = v1;
        }
    }
}

// ---------------------------------------------------------------------------
extern "C" void kernel_launch(void* const* d_in, const int* in_sizes, int n_in,
                              void* d_out, int out_size) {
    const int*   x    = (const int*)d_in[0];
    const float* emb  = (const float*)d_in[1];
    const float* pos  = (const float*)d_in[2];
    const float* wq   = (const float*)d_in[3];
    const float* wk   = (const float*)d_in[4];
    const float* wv   = (const float*)d_in[5];
    const float* linw = (const float*)d_in[6];
    const float* linb = (const float*)d_in[7];
    float* out = (float*)d_out;

    static int smem_set = 0;
    if (!smem_set) {
        cudaFuncSetAttribute(lm_head_f16_kernel,
                             cudaFuncAttributeMaxDynamicSharedMemorySize, LH_SMEM_BYTES);
        cudaFuncSetAttribute(qkv_mma_kernel,
                             cudaFuncAttributeMaxDynamicSharedMemorySize, QH_SMEM_BYTES);
        cudaFuncSetAttribute(attn_mma_kernel,
                             cudaFuncAttributeMaxDynamicSharedMemorySize, AH_SMEM_BYTES);
        smem_set = 1;
    }

    wqkv_prep_kernel<<<dim3(48, E_ / 32, D_ / 32), dim3(32, 8)>>>(wq, wk, wv);
    wt_prep_kernel<<<dim3(V_ / 32, HD_ / 32), dim3(32, 8)>>>(linw);
    embed_gelu_kernel<<<BS_, 256>>>(x, emb, pos);
    qkv_mma_kernel<<<dim3(BS_ / 128, 48), 256, QH_SMEM_BYTES>>>();
    attn_mma_kernel<<<dim3(S_ / 128, H_, B_), 256, AH_SMEM_BYTES>>>();
    lm_head_f16_kernel<<<dim3(BS_ / 128, V_ / 128), 256, LH_SMEM_BYTES>>>(linb, out);
}